// round 14
// baseline (speedup 1.0000x reference)
#include <cuda_runtime.h>
#include <math.h>
#include <stdint.h>

#define N_ENT  40000
#define N_REL  500
#define E_DIR  200000
#define E_TOT  250000
#define D_IN   128
#define D_EMB  256
#define NH     4

// ---------------- device scratch ----------------
__device__ float g_hr[N_ENT*D_EMB];
__device__ float g_hc[N_ENT*D_EMB];
__device__ float g_ent[N_ENT*D_EMB];
__device__ float g_prow[N_ENT*D_EMB];
__device__ float g_pcol[N_ENT*D_EMB];
__device__ float g_relp[N_REL*D_EMB];
__device__ float g_r[N_REL*D_EMB];
__device__ float g_rel2p[N_REL*D_EMB];
__device__ float g_x[N_ENT*D_EMB];
__device__ float g_B1[128*768];
__device__ float g_B1r[128*512];
__device__ float g_B2[256*512];
__device__ float g_B2r[256*256];
__device__ float g_sr[N_ENT*NH];
__device__ float g_sc[N_ENT*NH];
__device__ float g_srel[N_REL*NH];
__device__ float g_s2r[N_ENT];
__device__ float g_s2c[N_ENT];
__device__ float g_srel2[N_REL];
__device__ int   g_row[E_TOT];
__device__ int   g_col[E_TOT];
__device__ int   g_cnt[N_ENT];
__device__ int   g_off[N_ENT+1];
__device__ int   g_pos[N_ENT];
__device__ int   g_elist[E_TOT];
__device__ float g_colsum[D_EMB];
__device__ float g_colsq[D_EMB];

// ---------------- helpers ----------------
__device__ __forceinline__ void split2(float x, float y, uint32_t& hi, uint32_t& lo) {
    uint32_t xb = __float_as_uint(x) & 0xffff0000u;
    uint32_t yb = __float_as_uint(y) & 0xffff0000u;
    hi = (xb >> 16) | yb;
    float lx = x - __uint_as_float(xb);
    float ly = y - __uint_as_float(yb);
    asm("cvt.rn.bf16x2.f32 %0, %1, %2;" : "=r"(lo) : "f"(ly), "f"(lx));
}

__device__ __forceinline__ void mma16(float* c, const uint32_t* a, const uint32_t* b) {
    asm volatile(
        "mma.sync.aligned.m16n8k16.row.col.f32.bf16.bf16.f32 "
        "{%0,%1,%2,%3},{%4,%5,%6,%7},{%8,%9},{%0,%1,%2,%3};"
        : "+f"(c[0]), "+f"(c[1]), "+f"(c[2]), "+f"(c[3])
        : "r"(a[0]), "r"(a[1]), "r"(a[2]), "r"(a[3]), "r"(b[0]), "r"(b[1]));
}

// ---------------- init: counters + scalar accumulators ----------------
__global__ void k_init() {
    int i = blockIdx.x * blockDim.x + threadIdx.x;
    int stride = gridDim.x * blockDim.x;
    for (int idx = i; idx < N_ENT*NH; idx += stride) { g_sr[idx] = 0.f; g_sc[idx] = 0.f; }
    for (int idx = i; idx < N_ENT; idx += stride) {
        g_cnt[idx] = 0; g_s2r[idx] = 0.f; g_s2c[idx] = 0.f;
    }
    for (int idx = i; idx < N_REL*NH; idx += stride) g_srel[idx] = 0.f;
    for (int idx = i; idx < N_REL; idx += stride) g_srel2[idx] = 0.f;
    if (i < D_EMB) { g_colsum[i] = 0.f; g_colsq[i] = 0.f; }
}

// ---------------- weight repacks ----------------
__global__ void k_repackB1(const float* __restrict__ W_heads, const float* __restrict__ W_entities) {
    int idx = blockIdx.x * blockDim.x + threadIdx.x;
    if (idx >= 128*768) return;
    int k = idx / 768, c = idx % 768;
    float v;
    if (c < 512) {
        int part = c >> 8;
        int cc = c & 255;
        int h = cc >> 6, d = cc & 63;
        v = W_heads[h*384*64 + (part*128 + k)*64 + d];
    } else {
        v = W_entities[k*256 + (c - 512)];
    }
    g_B1[idx] = v;
}

__global__ void k_repackB1r(const float* __restrict__ W_heads, const float* __restrict__ gat_W) {
    int idx = blockIdx.x * blockDim.x + threadIdx.x;
    if (idx >= 128*512) return;
    int k = idx / 512, c = idx % 512;
    float v;
    if (c < 256) {
        int h = c >> 6, d = c & 63;
        v = W_heads[h*384*64 + (256 + k)*64 + d];
    } else {
        v = gat_W[k*256 + (c - 256)];
    }
    g_B1r[idx] = v;
}

__global__ void k_repackB2(const float* __restrict__ out_W) {
    int idx = blockIdx.x * blockDim.x + threadIdx.x;
    if (idx < 256*512) {
        int k = idx / 512, c = idx % 512;
        g_B2[idx] = (c < 256) ? out_W[k*256 + c] : out_W[(256 + k)*256 + (c - 256)];
    }
    if (idx < 256*256) {
        g_B2r[idx] = out_W[512*256 + idx];
    }
}

// ---------------- edge list + CSR build ----------------
__global__ void k_edges(const int* __restrict__ edge_index, const int* __restrict__ ind2) {
    int e = blockIdx.x * blockDim.x + threadIdx.x;
    if (e >= E_TOT) return;
    int r, c;
    if (e < E_DIR) { r = edge_index[E_DIR + e]; c = edge_index[e]; }
    else { int j = e - E_DIR; r = ind2[j*4 + 3]; c = ind2[j*4 + 0]; }
    g_row[e] = r; g_col[e] = c;
    atomicAdd(&g_cnt[r], 1);
}

#define SCAN_T 512
__global__ void k_scan() {
    __shared__ int s[SCAN_T];
    int t = threadIdx.x;
    const int CH = (N_ENT + SCAN_T - 1) / SCAN_T;
    int beg = t * CH;
    int fin = beg + CH; if (fin > N_ENT) fin = N_ENT;
    int sum = 0;
    for (int i = beg; i < fin; i++) sum += g_cnt[i];
    s[t] = sum;
    __syncthreads();
    for (int o = 1; o < SCAN_T; o <<= 1) {
        int v = (t >= o) ? s[t - o] : 0;
        __syncthreads();
        s[t] += v;
        __syncthreads();
    }
    int run = s[t] - sum;
    for (int i = beg; i < fin; i++) {
        g_off[i] = run;
        g_pos[i] = run;
        run += g_cnt[i];
    }
    if (t == SCAN_T - 1) g_off[N_ENT] = E_TOT;
}

__global__ void k_scatter() {
    int e = blockIdx.x * blockDim.x + threadIdx.x;
    if (e >= E_TOT) return;
    int r = g_row[e];
    int slot = atomicAdd(&g_pos[r], 1);
    g_elist[slot] = e;
}

// ---------------- 3x-bf16 GEMM, hi/lo-interleaved smem (LDS.64 mainloop) + fused scalars ----------------
// As: [row][kpair][{hi,lo}], row stride 40 words (16 kpairs*2 + pad 8)
// Bs: [kpair][n][{hi,lo}],  kpair stride 264 words (128 n*2 + pad 8)
__global__ __launch_bounds__(256, 1) void gemm_bf16(
    const float* __restrict__ A, const float* __restrict__ B,
    float* C0, float* C1, float* C2, float* C3, float* C4, float* C5,
    const float* __restrict__ avec,
    float* S0, float* S1, float* S2, float* S3, float* S4, float* S5,
    int sb0, int sb1, int sb2, int sb3, int sb4, int sb5,
    int sstride, int sgroups,
    int M, int K, int lda, int N)
{
    __shared__ uint32_t As[128*40];
    __shared__ uint32_t Bs[16*264];

    int tid  = threadIdx.x;
    int m0   = blockIdx.y * 128;
    int n0   = blockIdx.x * 128;
    int warp = tid >> 5;
    int lane = tid & 31;
    int g = lane >> 2;
    int t = lane & 3;
    int wm = warp >> 1;
    int wn = warp & 1;

    float* Cb;
    float* Sb;
    int sbase;
    switch (blockIdx.x) {
        case 0: Cb = C0; Sb = S0; sbase = sb0; break;
        case 1: Cb = C1; Sb = S1; sbase = sb1; break;
        case 2: Cb = C2; Sb = S2; sbase = sb2; break;
        case 3: Cb = C3; Sb = S3; sbase = sb3; break;
        case 4: Cb = C4; Sb = S4; sbase = sb4; break;
        default: Cb = C5; Sb = S5; sbase = sb5; break;
    }

    float acc[2][8][4];
    #pragma unroll
    for (int i = 0; i < 2; i++)
        #pragma unroll
        for (int j = 0; j < 8; j++)
            #pragma unroll
            for (int q = 0; q < 4; q++) acc[i][j][q] = 0.f;

    for (int k0 = 0; k0 < K; k0 += 32) {
        // fill A: [128 rows][16 kpairs] interleaved hi/lo
        #pragma unroll
        for (int i = 0; i < 4; i++) {
            int s = tid + i*256;
            int row = s >> 3;
            int w2  = (s & 7) << 1;            // kpair base (even): w2, w2+1
            float4 v = make_float4(0.f, 0.f, 0.f, 0.f);
            if (m0 + row < M)
                v = *(const float4*)(A + (size_t)(m0 + row)*lda + k0 + (w2 << 1));
            uint32_t h0, l0, h1, l1;
            split2(v.x, v.y, h0, l0);
            split2(v.z, v.w, h1, l1);
            *(uint4*)(As + row*40 + w2*2) = make_uint4(h0, l0, h1, l1);
        }
        // fill B: [16 kpairs][128 n] interleaved hi/lo
        #pragma unroll
        for (int i = 0; i < 2; i++) {
            int s = tid + i*256;
            int wr = s >> 5;
            int n4 = (s & 31) << 2;
            const float* b0p = B + (size_t)(k0 + 2*wr)*N + n0 + n4;
            float4 r0 = *(const float4*)(b0p);
            float4 r1 = *(const float4*)(b0p + N);
            uint32_t ha, la, hb, lb;
            split2(r0.x, r1.x, ha, la);
            split2(r0.y, r1.y, hb, lb);
            *(uint4*)(Bs + wr*264 + n4*2) = make_uint4(ha, la, hb, lb);
            split2(r0.z, r1.z, ha, la);
            split2(r0.w, r1.w, hb, lb);
            *(uint4*)(Bs + wr*264 + n4*2 + 4) = make_uint4(ha, la, hb, lb);
        }
        __syncthreads();

        #pragma unroll
        for (int ks = 0; ks < 2; ks++) {
            int kp = ks*8 + t;                 // kpair for a0/a1/b0
            uint32_t ahi[2][4], alo[2][4];
            #pragma unroll
            for (int i = 0; i < 2; i++) {
                int rb = wm*32 + i*16;
                uint2 u0 = *(uint2*)(As + (rb + g)*40     + kp*2);
                uint2 u1 = *(uint2*)(As + (rb + g + 8)*40 + kp*2);
                uint2 u2 = *(uint2*)(As + (rb + g)*40     + (kp + 4)*2);
                uint2 u3 = *(uint2*)(As + (rb + g + 8)*40 + (kp + 4)*2);
                ahi[i][0] = u0.x; alo[i][0] = u0.y;
                ahi[i][1] = u1.x; alo[i][1] = u1.y;
                ahi[i][2] = u2.x; alo[i][2] = u2.y;
                ahi[i][3] = u3.x; alo[i][3] = u3.y;
            }
            uint32_t bhi[8][2], blo[8][2];
            #pragma unroll
            for (int j = 0; j < 8; j++) {
                int nb = wn*64 + j*8 + g;
                uint2 v0 = *(uint2*)(Bs + kp*264       + nb*2);
                uint2 v1 = *(uint2*)(Bs + (kp + 4)*264 + nb*2);
                bhi[j][0] = v0.x; blo[j][0] = v0.y;
                bhi[j][1] = v1.x; blo[j][1] = v1.y;
            }
            #pragma unroll
            for (int i = 0; i < 2; i++)
                #pragma unroll
                for (int j = 0; j < 8; j++) {
                    mma16(acc[i][j], ahi[i], bhi[j]);
                    mma16(acc[i][j], ahi[i], blo[j]);
                    mma16(acc[i][j], alo[i], bhi[j]);
                }
        }
        __syncthreads();
    }

    // store C
    #pragma unroll
    for (int i = 0; i < 2; i++) {
        int r0 = m0 + wm*32 + i*16 + g;
        #pragma unroll
        for (int j = 0; j < 8; j++) {
            int col = wn*64 + j*8 + 2*t;
            if (r0 < M)
                *(float2*)(Cb + (size_t)r0*D_EMB + col) = make_float2(acc[i][j][0], acc[i][j][1]);
            if (r0 + 8 < M)
                *(float2*)(Cb + (size_t)(r0 + 8)*D_EMB + col) = make_float2(acc[i][j][2], acc[i][j][3]);
        }
    }

    // fused attention-scalar epilogue
    if (Sb) {
        float av0[8], av1[8];
        #pragma unroll
        for (int j = 0; j < 8; j++) {
            int col = n0 + wn*64 + j*8 + 2*t;
            av0[j] = avec[col & 255];
            av1[j] = avec[(col + 1) & 255];
        }
        int gidx = sbase + ((sgroups == 2) ? wn : 0);
        #pragma unroll
        for (int i = 0; i < 2; i++) {
            int r0 = m0 + wm*32 + i*16 + g;
            float d0 = 0.f, d1 = 0.f;
            #pragma unroll
            for (int j = 0; j < 8; j++) {
                d0 += acc[i][j][0]*av0[j] + acc[i][j][1]*av1[j];
                d1 += acc[i][j][2]*av0[j] + acc[i][j][3]*av1[j];
            }
            if (r0 < M)     atomicAdd(Sb + (size_t)r0*sstride + gidx, d0);
            if (r0 + 8 < M) atomicAdd(Sb + (size_t)(r0 + 8)*sstride + gidx, d1);
        }
    }
}

// ---------------- layer-1 single-pass row kernel, 2 warps per node ----------------
__global__ void k_row1(const int* __restrict__ et, const int* __restrict__ ind2) {
    int w_g  = (blockIdx.x * blockDim.x + threadIdx.x) >> 5;
    int lane = threadIdx.x & 31;
    if (w_g >= 2*N_ENT) return;
    int v    = w_g >> 1;
    int f    = ((w_g & 1) << 5) + lane;
    int h    = f >> 4;
    int off = g_off[v];
    int d   = g_off[v+1] - off;

    float srH = g_sr[v*NH + h];

    float4 acc = make_float4(0.f,0.f,0.f,0.f);
    float ws = 0.f;

    for (int i = 0; i < d; i++) {
        int e = g_elist[off + i];
        int c = g_col[e];
        float scH = g_sc[c*NH + h];
        float seH;
        const float4* hc = (const float4*)(g_hc + (size_t)c*D_EMB);
        float4 w0 = hc[f];
        float4 p0;
        if (e < E_DIR) {
            int tt = et[e];
            seH = g_srel[tt*NH + h];
            p0 = ((const float4*)(g_relp + tt*D_EMB))[f];
        } else {
            int j = e - E_DIR;
            int t0 = ind2[j*4+1], t1 = ind2[j*4+2];
            seH = g_srel[t0*NH + h] + g_srel[t1*NH + h];
            float4 q0 = ((const float4*)(g_relp + t0*D_EMB))[f];
            float4 q1 = ((const float4*)(g_relp + t1*D_EMB))[f];
            p0 = make_float4(q0.x+q1.x, q0.y+q1.y, q0.z+q1.z, q0.w+q1.w);
        }
        float z = srH + scH + seH;
        z = (z>0.f)?z:0.2f*z;
        float w = __expf(z);
        ws += w;
        acc.x += w*(w0.x+p0.x); acc.y += w*(w0.y+p0.y);
        acc.z += w*(w0.z+p0.z); acc.w += w*(w0.w+p0.w);
    }

    float inv = 1.f/(ws + 1e-16f);
    acc.x *= inv; acc.y *= inv; acc.z *= inv; acc.w *= inv;

    if (d > 0) {
        float4 hrv = ((const float4*)(g_hr + (size_t)v*D_EMB))[f];
        acc.x += hrv.x; acc.y += hrv.y; acc.z += hrv.z; acc.w += hrv.w;
    }
    acc.x = (acc.x>0.f)?acc.x:expm1f(acc.x);
    acc.y = (acc.y>0.f)?acc.y:expm1f(acc.y);
    acc.z = (acc.z>0.f)?acc.z:expm1f(acc.z);
    acc.w = (acc.w>0.f)?acc.w:expm1f(acc.w);
    ((float4*)(g_x + (size_t)v*D_EMB))[f] = acc;
}

// ---------------- layer-2 single-pass row kernel, 2 warps per node ----------------
__global__ void k_row2(const int* __restrict__ et, const int* __restrict__ ind2) {
    int w_g  = (blockIdx.x * blockDim.x + threadIdx.x) >> 5;
    int lane = threadIdx.x & 31;
    if (w_g >= 2*N_ENT) return;
    int v = w_g >> 1;
    int f = ((w_g & 1) << 5) + lane;
    int off = g_off[v];
    int d   = g_off[v+1] - off;

    float srv = g_s2r[v];

    float4 acc = make_float4(0.f,0.f,0.f,0.f);
    float ws = 0.f;

    for (int i = 0; i < d; i++) {
        int e = g_elist[off + i];
        int c = g_col[e];
        float se;
        float4 w0 = ((const float4*)(g_pcol + (size_t)c*D_EMB))[f];
        float4 p0;
        if (e < E_DIR) {
            int tt = et[e];
            se = g_srel2[tt];
            p0 = ((const float4*)(g_rel2p + tt*D_EMB))[f];
        } else {
            int j = e - E_DIR;
            int t0 = ind2[j*4+1], t1 = ind2[j*4+2];
            se = g_srel2[t0] + g_srel2[t1];
            float4 q0 = ((const float4*)(g_rel2p + t0*D_EMB))[f];
            float4 q1 = ((const float4*)(g_rel2p + t1*D_EMB))[f];
            p0 = make_float4(q0.x+q1.x, q0.y+q1.y, q0.z+q1.z, q0.w+q1.w);
        }
        float z = srv + g_s2c[c] + se;
        z = (z>0.f)?z:0.2f*z;
        float a = __expf(z);
        ws += a;
        acc.x += a*(w0.x+p0.x); acc.y += a*(w0.y+p0.y);
        acc.z += a*(w0.z+p0.z); acc.w += a*(w0.w+p0.w);
    }

    float inv = 1.f/(ws + 1e-16f);
    acc.x *= inv; acc.y *= inv; acc.z *= inv; acc.w *= inv;

    if (d > 0) {
        float4 hv = ((const float4*)(g_prow + (size_t)v*D_EMB))[f];
        acc.x += hv.x; acc.y += hv.y; acc.z += hv.z; acc.w += hv.w;
    }
    float4 ev = ((const float4*)(g_ent + (size_t)v*D_EMB))[f];
    acc.x = ((acc.x>0.f)?acc.x:expm1f(acc.x)) + ev.x;
    acc.y = ((acc.y>0.f)?acc.y:expm1f(acc.y)) + ev.y;
    acc.z = ((acc.z>0.f)?acc.z:expm1f(acc.z)) + ev.z;
    acc.w = ((acc.w>0.f)?acc.w:expm1f(acc.w)) + ev.w;
    ((float4*)(g_x + (size_t)v*D_EMB))[f] = acc;
}

// ---------------- BN stats + output ----------------
__global__ void k_stats() {
    int j = threadIdx.x;
    int v0 = blockIdx.x * 200;
    float s = 0.f, sq = 0.f;
    for (int v = v0; v < v0 + 200 && v < N_ENT; v++) {
        float z = g_x[(size_t)v*D_EMB + j];
        s += z; sq += z*z;
    }
    atomicAdd(&g_colsum[j], s);
    atomicAdd(&g_colsq[j], sq);
}

__global__ void k_bn_out(const float* __restrict__ gamma, const float* __restrict__ beta,
                         float* __restrict__ out) {
    int i = blockIdx.x * blockDim.x + threadIdx.x;
    if (i < N_ENT*D_EMB) {
        int j = i & 255;
        float mu  = g_colsum[j] * (1.f/N_ENT);
        float var = g_colsq[j] * (1.f/N_ENT) - mu*mu;
        out[i] = (g_x[i] - mu) * rsqrtf(var + 1e-5f) * gamma[j] + beta[j];
    } else if (i < N_ENT*D_EMB + N_REL*D_EMB) {
        out[i] = g_r[i - N_ENT*D_EMB];
    }
}

// ---------------- launch ----------------
extern "C" void kernel_launch(void* const* d_in, const int* in_sizes, int n_in,
                              void* d_out, int out_size) {
    const int*   edge_index = (const int*)d_in[0];
    const int*   edge_type  = (const int*)d_in[1];
    const int*   ind2       = (const int*)d_in[2];
    const float* init_embed = (const float*)d_in[3];
    const float* init_rel   = (const float*)d_in[4];
    const float* W_heads    = (const float*)d_in[5];
    const float* a_heads    = (const float*)d_in[6];
    const float* gat_W      = (const float*)d_in[7];
    const float* out_W      = (const float*)d_in[8];
    const float* out_a      = (const float*)d_in[9];
    const float* W_entities = (const float*)d_in[10];
    const float* bn_gamma   = (const float*)d_in[11];
    const float* bn_beta    = (const float*)d_in[12];
    float* out = (float*)d_out;

    float *p_hr, *p_hc, *p_ent, *p_prow, *p_pcol, *p_relp, *p_r, *p_rel2p, *p_x;
    float *p_B1, *p_B1r, *p_B2, *p_B2r;
    float *p_sr, *p_sc, *p_srel, *p_s2r, *p_s2c, *p_srel2;
    cudaGetSymbolAddress((void**)&p_hr,    g_hr);
    cudaGetSymbolAddress((void**)&p_hc,    g_hc);
    cudaGetSymbolAddress((void**)&p_ent,   g_ent);
    cudaGetSymbolAddress((void**)&p_prow,  g_prow);
    cudaGetSymbolAddress((void**)&p_pcol,  g_pcol);
    cudaGetSymbolAddress((void**)&p_relp,  g_relp);
    cudaGetSymbolAddress((void**)&p_r,     g_r);
    cudaGetSymbolAddress((void**)&p_rel2p, g_rel2p);
    cudaGetSymbolAddress((void**)&p_x,     g_x);
    cudaGetSymbolAddress((void**)&p_B1,    g_B1);
    cudaGetSymbolAddress((void**)&p_B1r,   g_B1r);
    cudaGetSymbolAddress((void**)&p_B2,    g_B2);
    cudaGetSymbolAddress((void**)&p_B2r,   g_B2r);
    cudaGetSymbolAddress((void**)&p_sr,    g_sr);
    cudaGetSymbolAddress((void**)&p_sc,    g_sc);
    cudaGetSymbolAddress((void**)&p_srel,  g_srel);
    cudaGetSymbolAddress((void**)&p_s2r,   g_s2r);
    cudaGetSymbolAddress((void**)&p_s2c,   g_s2c);
    cudaGetSymbolAddress((void**)&p_srel2, g_srel2);

    const int TB = 256;
    k_init<<<160, TB>>>();
    k_repackB1<<<(128*768 + TB-1)/TB, TB>>>(W_heads, W_entities);
    k_repackB1r<<<(128*512 + TB-1)/TB, TB>>>(W_heads, gat_W);
    k_repackB2<<<(256*512 + TB-1)/TB, TB>>>(out_W);
    k_edges<<<(E_TOT + TB-1)/TB, TB>>>(edge_index, ind2);
    k_scan<<<1, SCAN_T>>>();
    k_scatter<<<(E_TOT + TB-1)/TB, TB>>>();

    // layer-1 GEMMs (scalars fused)
    gemm_bf16<<<dim3(6, (N_ENT + 127)/128), 256>>>(
        init_embed, p_B1,
        p_hr, p_hr + 128, p_hc, p_hc + 128, p_ent, p_ent + 128,
        a_heads,
        p_sr, p_sr, p_sc, p_sc, (float*)0, (float*)0,
        0, 2, 0, 2, 0, 0,
        NH, 2,
        N_ENT, 128, 128, 768);
    gemm_bf16<<<dim3(4, (N_REL + 127)/128), 256>>>(
        init_rel, p_B1r,
        p_relp, p_relp + 128, p_r, p_r + 128, p_r, p_r,
        a_heads,
        p_srel, p_srel, (float*)0, (float*)0, (float*)0, (float*)0,
        0, 2, 0, 0, 0, 0,
        NH, 2,
        N_REL, 128, 128, 512);

    // layer-1 attention
    k_row1<<<(2*N_ENT*32 + TB-1)/TB, TB>>>(edge_type, ind2);

    // layer-2 GEMMs (scalars fused)
    gemm_bf16<<<dim3(4, (N_ENT + 127)/128), 256>>>(
        p_x, p_B2,
        p_prow, p_prow + 128, p_pcol, p_pcol + 128, p_pcol, p_pcol,
        out_a,
        p_s2r, p_s2r, p_s2c, p_s2c, (float*)0, (float*)0,
        0, 0, 0, 0, 0, 0,
        1, 1,
        N_ENT, 256, 256, 512);
    gemm_bf16<<<dim3(2, (N_REL + 127)/128), 256>>>(
        p_r, p_B2r,
        p_rel2p, p_rel2p + 128, p_rel2p, p_rel2p, p_rel2p, p_rel2p,
        out_a,
        p_srel2, p_srel2, (float*)0, (float*)0, (float*)0, (float*)0,
        0, 0, 0, 0, 0, 0,
        1, 1,
        N_REL, 256, 256, 256);

    // layer-2 attention
    k_row2<<<(2*N_ENT*32 + TB-1)/TB, TB>>>(edge_type, ind2);

    k_stats<<<200, 256>>>();
    k_bn_out<<<(N_ENT*D_EMB + N_REL*D_EMB + TB-1)/TB, TB>>>(bn_gamma, bn_beta, out);
}

// round 15
// speedup vs baseline: 1.0126x; 1.0126x over previous
#include <cuda_runtime.h>
#include <math.h>
#include <stdint.h>

#define N_ENT  40000
#define N_REL  500
#define E_DIR  200000
#define E_TOT  250000
#define D_IN   128
#define D_EMB  256
#define NH     4

// ---------------- device scratch ----------------
__device__ float g_hr[N_ENT*D_EMB];
__device__ float g_hc[N_ENT*D_EMB];
__device__ float g_ent[N_ENT*D_EMB];
__device__ float g_prow[N_ENT*D_EMB];
__device__ float g_pcol[N_ENT*D_EMB];
__device__ float g_relp[N_REL*D_EMB];
__device__ float g_r[N_REL*D_EMB];
__device__ float g_rel2p[N_REL*D_EMB];
__device__ float g_x[N_ENT*D_EMB];
__device__ float g_B1[128*768];
__device__ float g_B1r[128*512];
__device__ float g_B2[256*512];
__device__ float g_B2r[256*256];
__device__ float g_sr[N_ENT*NH];
__device__ float g_sc[N_ENT*NH];
__device__ float g_srel[N_REL*NH];
__device__ float g_s2r[N_ENT];
__device__ float g_s2c[N_ENT];
__device__ float g_srel2[N_REL];
__device__ int   g_row[E_TOT];
__device__ int   g_col[E_TOT];
__device__ int   g_cnt[N_ENT];
__device__ int   g_off[N_ENT+1];
__device__ int   g_pos[N_ENT];
__device__ int   g_elist[E_TOT];
__device__ float g_colsum[D_EMB];
__device__ float g_colsq[D_EMB];

// ---------------- helpers ----------------
__device__ __forceinline__ void split2(float x, float y, uint32_t& hi, uint32_t& lo) {
    uint32_t xb = __float_as_uint(x) & 0xffff0000u;
    uint32_t yb = __float_as_uint(y) & 0xffff0000u;
    hi = (xb >> 16) | yb;
    float lx = x - __uint_as_float(xb);
    float ly = y - __uint_as_float(yb);
    asm("cvt.rn.bf16x2.f32 %0, %1, %2;" : "=r"(lo) : "f"(ly), "f"(lx));
}

__device__ __forceinline__ void mma16(float* c, const uint32_t* a, const uint32_t* b) {
    asm volatile(
        "mma.sync.aligned.m16n8k16.row.col.f32.bf16.bf16.f32 "
        "{%0,%1,%2,%3},{%4,%5,%6,%7},{%8,%9},{%0,%1,%2,%3};"
        : "+f"(c[0]), "+f"(c[1]), "+f"(c[2]), "+f"(c[3])
        : "r"(a[0]), "r"(a[1]), "r"(a[2]), "r"(a[3]), "r"(b[0]), "r"(b[1]));
}

// ---------------- init: counters + scalar accumulators ----------------
__global__ void k_init() {
    int i = blockIdx.x * blockDim.x + threadIdx.x;
    int stride = gridDim.x * blockDim.x;
    for (int idx = i; idx < N_ENT*NH; idx += stride) { g_sr[idx] = 0.f; g_sc[idx] = 0.f; }
    for (int idx = i; idx < N_ENT; idx += stride) {
        g_cnt[idx] = 0; g_s2r[idx] = 0.f; g_s2c[idx] = 0.f;
    }
    for (int idx = i; idx < N_REL*NH; idx += stride) g_srel[idx] = 0.f;
    for (int idx = i; idx < N_REL; idx += stride) g_srel2[idx] = 0.f;
    if (i < D_EMB) { g_colsum[i] = 0.f; g_colsq[i] = 0.f; }
}

// ---------------- fused prep: all weight repacks + edge list build ----------------
#define PREP_B1   (128*768)                       // 98304
#define PREP_B1R  (PREP_B1 + 128*512)             // +65536
#define PREP_B2   (PREP_B1R + 256*512)            // +131072
#define PREP_B2R  (PREP_B2 + 256*256)             // +65536
#define PREP_EDG  (PREP_B2R + E_TOT)              // +250000
__global__ void k_prep(const float* __restrict__ W_heads, const float* __restrict__ W_entities,
                       const float* __restrict__ gat_W, const float* __restrict__ out_W,
                       const int* __restrict__ edge_index, const int* __restrict__ ind2) {
    int i = blockIdx.x * blockDim.x + threadIdx.x;
    if (i < PREP_B1) {
        int idx = i;
        int k = idx / 768, c = idx % 768;
        float v;
        if (c < 512) {
            int part = c >> 8;
            int cc = c & 255;
            int h = cc >> 6, d = cc & 63;
            v = W_heads[h*384*64 + (part*128 + k)*64 + d];
        } else {
            v = W_entities[k*256 + (c - 512)];
        }
        g_B1[idx] = v;
    } else if (i < PREP_B1R) {
        int idx = i - PREP_B1;
        int k = idx / 512, c = idx % 512;
        float v;
        if (c < 256) {
            int h = c >> 6, d = c & 63;
            v = W_heads[h*384*64 + (256 + k)*64 + d];
        } else {
            v = gat_W[k*256 + (c - 256)];
        }
        g_B1r[idx] = v;
    } else if (i < PREP_B2) {
        int idx = i - PREP_B1R;
        int k = idx / 512, c = idx % 512;
        g_B2[idx] = (c < 256) ? out_W[k*256 + c] : out_W[(256 + k)*256 + (c - 256)];
    } else if (i < PREP_B2R) {
        int idx = i - PREP_B2;
        g_B2r[idx] = out_W[512*256 + idx];
    } else if (i < PREP_EDG) {
        int e = i - PREP_B2R;
        int r, c;
        if (e < E_DIR) { r = edge_index[E_DIR + e]; c = edge_index[e]; }
        else { int j = e - E_DIR; r = ind2[j*4 + 3]; c = ind2[j*4 + 0]; }
        g_row[e] = r; g_col[e] = c;
        atomicAdd(&g_cnt[r], 1);
    }
}

#define SCAN_T 1024
__global__ void k_scan() {
    __shared__ int s[SCAN_T];
    int t = threadIdx.x;
    const int CH = (N_ENT + SCAN_T - 1) / SCAN_T;   // 40
    int beg = t * CH;
    int fin = beg + CH; if (fin > N_ENT) fin = N_ENT;
    int sum = 0;
    for (int i = beg; i < fin; i++) sum += g_cnt[i];
    s[t] = sum;
    __syncthreads();
    for (int o = 1; o < SCAN_T; o <<= 1) {
        int v = (t >= o) ? s[t - o] : 0;
        __syncthreads();
        s[t] += v;
        __syncthreads();
    }
    int run = s[t] - sum;
    for (int i = beg; i < fin; i++) {
        g_off[i] = run;
        g_pos[i] = run;
        run += g_cnt[i];
    }
    if (t == SCAN_T - 1) g_off[N_ENT] = E_TOT;
}

__global__ void k_scatter() {
    int e = blockIdx.x * blockDim.x + threadIdx.x;
    if (e >= E_TOT) return;
    int r = g_row[e];
    int slot = atomicAdd(&g_pos[r], 1);
    g_elist[slot] = e;
}

// ---------------- 3x-bf16 tensor-core GEMM (R13 frozen) + fused attention-scalar epilogue ----------------
__global__ __launch_bounds__(256, 1) void gemm_bf16(
    const float* __restrict__ A, const float* __restrict__ B,
    float* C0, float* C1, float* C2, float* C3, float* C4, float* C5,
    const float* __restrict__ avec,
    float* S0, float* S1, float* S2, float* S3, float* S4, float* S5,
    int sb0, int sb1, int sb2, int sb3, int sb4, int sb5,
    int sstride, int sgroups,
    int M, int K, int lda, int N)
{
    __shared__ uint32_t Ah[128*20];
    __shared__ uint32_t Al[128*20];
    __shared__ uint32_t Bh[16*136];
    __shared__ uint32_t Bl[16*136];

    int tid  = threadIdx.x;
    int m0   = blockIdx.y * 128;
    int n0   = blockIdx.x * 128;
    int warp = tid >> 5;
    int lane = tid & 31;
    int g = lane >> 2;
    int t = lane & 3;
    int wm = warp >> 1;
    int wn = warp & 1;

    float* Cb;
    float* Sb;
    int sbase;
    switch (blockIdx.x) {
        case 0: Cb = C0; Sb = S0; sbase = sb0; break;
        case 1: Cb = C1; Sb = S1; sbase = sb1; break;
        case 2: Cb = C2; Sb = S2; sbase = sb2; break;
        case 3: Cb = C3; Sb = S3; sbase = sb3; break;
        case 4: Cb = C4; Sb = S4; sbase = sb4; break;
        default: Cb = C5; Sb = S5; sbase = sb5; break;
    }

    float acc[2][8][4];
    #pragma unroll
    for (int i = 0; i < 2; i++)
        #pragma unroll
        for (int j = 0; j < 8; j++)
            #pragma unroll
            for (int q = 0; q < 4; q++) acc[i][j][q] = 0.f;

    for (int k0 = 0; k0 < K; k0 += 32) {
        #pragma unroll
        for (int i = 0; i < 4; i++) {
            int s = tid + i*256;
            int row = s >> 3;
            int w2  = (s & 7) << 1;
            float4 v = make_float4(0.f, 0.f, 0.f, 0.f);
            if (m0 + row < M)
                v = *(const float4*)(A + (size_t)(m0 + row)*lda + k0 + (w2 << 1));
            uint32_t h0, l0, h1, l1;
            split2(v.x, v.y, h0, l0);
            split2(v.z, v.w, h1, l1);
            Ah[row*20 + w2]     = h0;
            Ah[row*20 + w2 + 1] = h1;
            Al[row*20 + w2]     = l0;
            Al[row*20 + w2 + 1] = l1;
        }
        #pragma unroll
        for (int i = 0; i < 2; i++) {
            int s = tid + i*256;
            int wr = s >> 5;
            int n4 = (s & 31) << 2;
            const float* b0p = B + (size_t)(k0 + 2*wr)*N + n0 + n4;
            float4 r0 = *(const float4*)(b0p);
            float4 r1 = *(const float4*)(b0p + N);
            uint32_t h, l;
            split2(r0.x, r1.x, h, l); Bh[wr*136 + n4]     = h; Bl[wr*136 + n4]     = l;
            split2(r0.y, r1.y, h, l); Bh[wr*136 + n4 + 1] = h; Bl[wr*136 + n4 + 1] = l;
            split2(r0.z, r1.z, h, l); Bh[wr*136 + n4 + 2] = h; Bl[wr*136 + n4 + 2] = l;
            split2(r0.w, r1.w, h, l); Bh[wr*136 + n4 + 3] = h; Bl[wr*136 + n4 + 3] = l;
        }
        __syncthreads();

        #pragma unroll
        for (int ks = 0; ks < 2; ks++) {
            int kw = ks * 8;
            uint32_t ahi[2][4], alo[2][4];
            #pragma unroll
            for (int i = 0; i < 2; i++) {
                int rb = wm*32 + i*16;
                ahi[i][0] = Ah[(rb + g)*20     + kw + t];
                ahi[i][1] = Ah[(rb + g + 8)*20 + kw + t];
                ahi[i][2] = Ah[(rb + g)*20     + kw + t + 4];
                ahi[i][3] = Ah[(rb + g + 8)*20 + kw + t + 4];
                alo[i][0] = Al[(rb + g)*20     + kw + t];
                alo[i][1] = Al[(rb + g + 8)*20 + kw + t];
                alo[i][2] = Al[(rb + g)*20     + kw + t + 4];
                alo[i][3] = Al[(rb + g + 8)*20 + kw + t + 4];
            }
            uint32_t bhi[8][2], blo[8][2];
            #pragma unroll
            for (int j = 0; j < 8; j++) {
                int nb = wn*64 + j*8 + g;
                bhi[j][0] = Bh[(kw + t)*136     + nb];
                bhi[j][1] = Bh[(kw + t + 4)*136 + nb];
                blo[j][0] = Bl[(kw + t)*136     + nb];
                blo[j][1] = Bl[(kw + t + 4)*136 + nb];
            }
            #pragma unroll
            for (int i = 0; i < 2; i++)
                #pragma unroll
                for (int j = 0; j < 8; j++) {
                    mma16(acc[i][j], ahi[i], bhi[j]);
                    mma16(acc[i][j], ahi[i], blo[j]);
                    mma16(acc[i][j], alo[i], bhi[j]);
                }
        }
        __syncthreads();
    }

    // store C
    #pragma unroll
    for (int i = 0; i < 2; i++) {
        int r0 = m0 + wm*32 + i*16 + g;
        #pragma unroll
        for (int j = 0; j < 8; j++) {
            int col = wn*64 + j*8 + 2*t;
            if (r0 < M)
                *(float2*)(Cb + (size_t)r0*D_EMB + col) = make_float2(acc[i][j][0], acc[i][j][1]);
            if (r0 + 8 < M)
                *(float2*)(Cb + (size_t)(r0 + 8)*D_EMB + col) = make_float2(acc[i][j][2], acc[i][j][3]);
        }
    }

    // fused attention-scalar epilogue
    if (Sb) {
        float av0[8], av1[8];
        #pragma unroll
        for (int j = 0; j < 8; j++) {
            int col = n0 + wn*64 + j*8 + 2*t;
            av0[j] = avec[col & 255];
            av1[j] = avec[(col + 1) & 255];
        }
        int gidx = sbase + ((sgroups == 2) ? wn : 0);
        #pragma unroll
        for (int i = 0; i < 2; i++) {
            int r0 = m0 + wm*32 + i*16 + g;
            float d0 = 0.f, d1 = 0.f;
            #pragma unroll
            for (int j = 0; j < 8; j++) {
                d0 += acc[i][j][0]*av0[j] + acc[i][j][1]*av1[j];
                d1 += acc[i][j][2]*av0[j] + acc[i][j][3]*av1[j];
            }
            if (r0 < M)     atomicAdd(Sb + (size_t)r0*sstride + gidx, d0);
            if (r0 + 8 < M) atomicAdd(Sb + (size_t)(r0 + 8)*sstride + gidx, d1);
        }
    }
}

// ---------------- layer-1 single-pass row kernel, 2 warps per node ----------------
__global__ void k_row1(const int* __restrict__ et, const int* __restrict__ ind2) {
    int w_g  = (blockIdx.x * blockDim.x + threadIdx.x) >> 5;
    int lane = threadIdx.x & 31;
    if (w_g >= 2*N_ENT) return;
    int v    = w_g >> 1;
    int f    = ((w_g & 1) << 5) + lane;
    int h    = f >> 4;
    int off = g_off[v];
    int d   = g_off[v+1] - off;

    float srH = g_sr[v*NH + h];

    float4 acc = make_float4(0.f,0.f,0.f,0.f);
    float ws = 0.f;

    for (int i = 0; i < d; i++) {
        int e = g_elist[off + i];
        int c = g_col[e];
        float scH = g_sc[c*NH + h];
        float seH;
        const float4* hc = (const float4*)(g_hc + (size_t)c*D_EMB);
        float4 w0 = hc[f];
        float4 p0;
        if (e < E_DIR) {
            int tt = et[e];
            seH = g_srel[tt*NH + h];
            p0 = ((const float4*)(g_relp + tt*D_EMB))[f];
        } else {
            int j = e - E_DIR;
            int t0 = ind2[j*4+1], t1 = ind2[j*4+2];
            seH = g_srel[t0*NH + h] + g_srel[t1*NH + h];
            float4 q0 = ((const float4*)(g_relp + t0*D_EMB))[f];
            float4 q1 = ((const float4*)(g_relp + t1*D_EMB))[f];
            p0 = make_float4(q0.x+q1.x, q0.y+q1.y, q0.z+q1.z, q0.w+q1.w);
        }
        float z = srH + scH + seH;
        z = (z>0.f)?z:0.2f*z;
        float w = __expf(z);
        ws += w;
        acc.x += w*(w0.x+p0.x); acc.y += w*(w0.y+p0.y);
        acc.z += w*(w0.z+p0.z); acc.w += w*(w0.w+p0.w);
    }

    float inv = 1.f/(ws + 1e-16f);
    acc.x *= inv; acc.y *= inv; acc.z *= inv; acc.w *= inv;

    if (d > 0) {
        float4 hrv = ((const float4*)(g_hr + (size_t)v*D_EMB))[f];
        acc.x += hrv.x; acc.y += hrv.y; acc.z += hrv.z; acc.w += hrv.w;
    }
    acc.x = (acc.x>0.f)?acc.x:expm1f(acc.x);
    acc.y = (acc.y>0.f)?acc.y:expm1f(acc.y);
    acc.z = (acc.z>0.f)?acc.z:expm1f(acc.z);
    acc.w = (acc.w>0.f)?acc.w:expm1f(acc.w);
    ((float4*)(g_x + (size_t)v*D_EMB))[f] = acc;
}

// ---------------- layer-2 single-pass row kernel, 2 warps per node ----------------
__global__ void k_row2(const int* __restrict__ et, const int* __restrict__ ind2) {
    int w_g  = (blockIdx.x * blockDim.x + threadIdx.x) >> 5;
    int lane = threadIdx.x & 31;
    if (w_g >= 2*N_ENT) return;
    int v = w_g >> 1;
    int f = ((w_g & 1) << 5) + lane;
    int off = g_off[v];
    int d   = g_off[v+1] - off;

    float srv = g_s2r[v];

    float4 acc = make_float4(0.f,0.f,0.f,0.f);
    float ws = 0.f;

    for (int i = 0; i < d; i++) {
        int e = g_elist[off + i];
        int c = g_col[e];
        float se;
        float4 w0 = ((const float4*)(g_pcol + (size_t)c*D_EMB))[f];
        float4 p0;
        if (e < E_DIR) {
            int tt = et[e];
            se = g_srel2[tt];
            p0 = ((const float4*)(g_rel2p + tt*D_EMB))[f];
        } else {
            int j = e - E_DIR;
            int t0 = ind2[j*4+1], t1 = ind2[j*4+2];
            se = g_srel2[t0] + g_srel2[t1];
            float4 q0 = ((const float4*)(g_rel2p + t0*D_EMB))[f];
            float4 q1 = ((const float4*)(g_rel2p + t1*D_EMB))[f];
            p0 = make_float4(q0.x+q1.x, q0.y+q1.y, q0.z+q1.z, q0.w+q1.w);
        }
        float z = srv + g_s2c[c] + se;
        z = (z>0.f)?z:0.2f*z;
        float a = __expf(z);
        ws += a;
        acc.x += a*(w0.x+p0.x); acc.y += a*(w0.y+p0.y);
        acc.z += a*(w0.z+p0.z); acc.w += a*(w0.w+p0.w);
    }

    float inv = 1.f/(ws + 1e-16f);
    acc.x *= inv; acc.y *= inv; acc.z *= inv; acc.w *= inv;

    if (d > 0) {
        float4 hv = ((const float4*)(g_prow + (size_t)v*D_EMB))[f];
        acc.x += hv.x; acc.y += hv.y; acc.z += hv.z; acc.w += hv.w;
    }
    float4 ev = ((const float4*)(g_ent + (size_t)v*D_EMB))[f];
    acc.x = ((acc.x>0.f)?acc.x:expm1f(acc.x)) + ev.x;
    acc.y = ((acc.y>0.f)?acc.y:expm1f(acc.y)) + ev.y;
    acc.z = ((acc.z>0.f)?acc.z:expm1f(acc.z)) + ev.z;
    acc.w = ((acc.w>0.f)?acc.w:expm1f(acc.w)) + ev.w;
    ((float4*)(g_x + (size_t)v*D_EMB))[f] = acc;
}

// ---------------- BN stats + output ----------------
__global__ void k_stats() {
    int j = threadIdx.x;
    int v0 = blockIdx.x * 200;
    float s = 0.f, sq = 0.f;
    for (int v = v0; v < v0 + 200 && v < N_ENT; v++) {
        float z = g_x[(size_t)v*D_EMB + j];
        s += z; sq += z*z;
    }
    atomicAdd(&g_colsum[j], s);
    atomicAdd(&g_colsq[j], sq);
}

__global__ void k_bn_out(const float* __restrict__ gamma, const float* __restrict__ beta,
                         float* __restrict__ out) {
    int i = blockIdx.x * blockDim.x + threadIdx.x;
    if (i < N_ENT*D_EMB) {
        int j = i & 255;
        float mu  = g_colsum[j] * (1.f/N_ENT);
        float var = g_colsq[j] * (1.f/N_ENT) - mu*mu;
        out[i] = (g_x[i] - mu) * rsqrtf(var + 1e-5f) * gamma[j] + beta[j];
    } else if (i < N_ENT*D_EMB + N_REL*D_EMB) {
        out[i] = g_r[i - N_ENT*D_EMB];
    }
}

// ---------------- launch ----------------
extern "C" void kernel_launch(void* const* d_in, const int* in_sizes, int n_in,
                              void* d_out, int out_size) {
    const int*   edge_index = (const int*)d_in[0];
    const int*   edge_type  = (const int*)d_in[1];
    const int*   ind2       = (const int*)d_in[2];
    const float* init_embed = (const float*)d_in[3];
    const float* init_rel   = (const float*)d_in[4];
    const float* W_heads    = (const float*)d_in[5];
    const float* a_heads    = (const float*)d_in[6];
    const float* gat_W      = (const float*)d_in[7];
    const float* out_W      = (const float*)d_in[8];
    const float* out_a      = (const float*)d_in[9];
    const float* W_entities = (const float*)d_in[10];
    const float* bn_gamma   = (const float*)d_in[11];
    const float* bn_beta    = (const float*)d_in[12];
    float* out = (float*)d_out;

    float *p_hr, *p_hc, *p_ent, *p_prow, *p_pcol, *p_relp, *p_r, *p_rel2p, *p_x;
    float *p_B1, *p_B1r, *p_B2, *p_B2r;
    float *p_sr, *p_sc, *p_srel, *p_s2r, *p_s2c, *p_srel2;
    cudaGetSymbolAddress((void**)&p_hr,    g_hr);
    cudaGetSymbolAddress((void**)&p_hc,    g_hc);
    cudaGetSymbolAddress((void**)&p_ent,   g_ent);
    cudaGetSymbolAddress((void**)&p_prow,  g_prow);
    cudaGetSymbolAddress((void**)&p_pcol,  g_pcol);
    cudaGetSymbolAddress((void**)&p_relp,  g_relp);
    cudaGetSymbolAddress((void**)&p_r,     g_r);
    cudaGetSymbolAddress((void**)&p_rel2p, g_rel2p);
    cudaGetSymbolAddress((void**)&p_x,     g_x);
    cudaGetSymbolAddress((void**)&p_B1,    g_B1);
    cudaGetSymbolAddress((void**)&p_B1r,   g_B1r);
    cudaGetSymbolAddress((void**)&p_B2,    g_B2);
    cudaGetSymbolAddress((void**)&p_B2r,   g_B2r);
    cudaGetSymbolAddress((void**)&p_sr,    g_sr);
    cudaGetSymbolAddress((void**)&p_sc,    g_sc);
    cudaGetSymbolAddress((void**)&p_srel,  g_srel);
    cudaGetSymbolAddress((void**)&p_s2r,   g_s2r);
    cudaGetSymbolAddress((void**)&p_s2c,   g_s2c);
    cudaGetSymbolAddress((void**)&p_srel2, g_srel2);

    const int TB = 256;
    k_init<<<160, TB>>>();
    k_prep<<<(PREP_EDG + TB-1)/TB, TB>>>(W_heads, W_entities, gat_W, out_W, edge_index, ind2);
    k_scan<<<1, SCAN_T>>>();
    k_scatter<<<(E_TOT + TB-1)/TB, TB>>>();

    // layer-1 GEMMs (scalars fused)
    gemm_bf16<<<dim3(6, (N_ENT + 127)/128), 256>>>(
        init_embed, p_B1,
        p_hr, p_hr + 128, p_hc, p_hc + 128, p_ent, p_ent + 128,
        a_heads,
        p_sr, p_sr, p_sc, p_sc, (float*)0, (float*)0,
        0, 2, 0, 2, 0, 0,
        NH, 2,
        N_ENT, 128, 128, 768);
    gemm_bf16<<<dim3(4, (N_REL + 127)/128), 256>>>(
        init_rel, p_B1r,
        p_relp, p_relp + 128, p_r, p_r + 128, p_r, p_r,
        a_heads,
        p_srel, p_srel, (float*)0, (float*)0, (float*)0, (float*)0,
        0, 2, 0, 0, 0, 0,
        NH, 2,
        N_REL, 128, 128, 512);

    // layer-1 attention
    k_row1<<<(2*N_ENT*32 + TB-1)/TB, TB>>>(edge_type, ind2);

    // layer-2 GEMMs (scalars fused)
    gemm_bf16<<<dim3(4, (N_ENT + 127)/128), 256>>>(
        p_x, p_B2,
        p_prow, p_prow + 128, p_pcol, p_pcol + 128, p_pcol, p_pcol,
        out_a,
        p_s2r, p_s2r, p_s2c, p_s2c, (float*)0, (float*)0,
        0, 0, 0, 0, 0, 0,
        1, 1,
        N_ENT, 256, 256, 512);
    gemm_bf16<<<dim3(2, (N_REL + 127)/128), 256>>>(
        p_r, p_B2r,
        p_rel2p, p_rel2p + 128, p_rel2p, p_rel2p, p_rel2p, p_rel2p,
        out_a,
        p_srel2, p_srel2, (float*)0, (float*)0, (float*)0, (float*)0,
        0, 0, 0, 0, 0, 0,
        1, 1,
        N_REL, 256, 256, 256);

    // layer-2 attention
    k_row2<<<(2*N_ENT*32 + TB-1)/TB, TB>>>(edge_type, ind2);

    k_stats<<<200, 256>>>();
    k_bn_out<<<(N_ENT*D_EMB + N_REL*D_EMB + TB-1)/TB, TB>>>(bn_gamma, bn_beta, out);
}

// round 16
// speedup vs baseline: 1.1435x; 1.1292x over previous
#include <cuda_runtime.h>
#include <math.h>
#include <stdint.h>

#define N_ENT  40000
#define N_REL  500
#define E_DIR  200000
#define E_TOT  250000
#define D_IN   128
#define D_EMB  256
#define NH     4

// ---------------- device scratch ----------------
__device__ float g_hr[N_ENT*D_EMB];
__device__ float g_hc[N_ENT*D_EMB];
__device__ float g_ent[N_ENT*D_EMB];
__device__ float g_prow[N_ENT*D_EMB];
__device__ float g_pcol[N_ENT*D_EMB];
__device__ float g_relp[N_REL*D_EMB];
__device__ float g_r[N_REL*D_EMB];
__device__ float g_rel2p[N_REL*D_EMB];
__device__ float g_x[N_ENT*D_EMB];
__device__ float g_B1[128*768];
__device__ float g_B1r[128*512];
__device__ float g_B2[256*512];
__device__ float g_B2r[256*256];
__device__ float g_sr[N_ENT*NH];
__device__ float g_sc[N_ENT*NH];
__device__ float g_srel[N_REL*NH];
__device__ float g_s2r[N_ENT];
__device__ float g_s2c[N_ENT];
__device__ float g_srel2[N_REL];
__device__ int   g_row[E_TOT];
__device__ int   g_col[E_TOT];
__device__ int   g_cnt[N_ENT];
__device__ int   g_off[N_ENT+1];
__device__ int   g_pos[N_ENT];
__device__ int   g_elist[E_TOT];
__device__ float g_colsum[D_EMB];
__device__ float g_colsq[D_EMB];

// ---------------- helpers ----------------
__device__ __forceinline__ void split2(float x, float y, uint32_t& hi, uint32_t& lo) {
    uint32_t xb = __float_as_uint(x) & 0xffff0000u;
    uint32_t yb = __float_as_uint(y) & 0xffff0000u;
    hi = (xb >> 16) | yb;
    float lx = x - __uint_as_float(xb);
    float ly = y - __uint_as_float(yb);
    asm("cvt.rn.bf16x2.f32 %0, %1, %2;" : "=r"(lo) : "f"(ly), "f"(lx));
}

__device__ __forceinline__ void mma16(float* c, const uint32_t* a, const uint32_t* b) {
    asm volatile(
        "mma.sync.aligned.m16n8k16.row.col.f32.bf16.bf16.f32 "
        "{%0,%1,%2,%3},{%4,%5,%6,%7},{%8,%9},{%0,%1,%2,%3};"
        : "+f"(c[0]), "+f"(c[1]), "+f"(c[2]), "+f"(c[3])
        : "r"(a[0]), "r"(a[1]), "r"(a[2]), "r"(a[3]), "r"(b[0]), "r"(b[1]));
}

// ---------------- init: counters + scalar accumulators ----------------
__global__ void k_init() {
    int i = blockIdx.x * blockDim.x + threadIdx.x;
    int stride = gridDim.x * blockDim.x;
    for (int idx = i; idx < N_ENT*NH; idx += stride) { g_sr[idx] = 0.f; g_sc[idx] = 0.f; }
    for (int idx = i; idx < N_ENT; idx += stride) {
        g_cnt[idx] = 0; g_s2r[idx] = 0.f; g_s2c[idx] = 0.f;
    }
    for (int idx = i; idx < N_REL*NH; idx += stride) g_srel[idx] = 0.f;
    for (int idx = i; idx < N_REL; idx += stride) g_srel2[idx] = 0.f;
    if (i < D_EMB) { g_colsum[i] = 0.f; g_colsq[i] = 0.f; }
}

// ---------------- fused prep: all weight repacks + edge list build ----------------
#define PREP_B1   (128*768)
#define PREP_B1R  (PREP_B1 + 128*512)
#define PREP_B2   (PREP_B1R + 256*512)
#define PREP_B2R  (PREP_B2 + 256*256)
#define PREP_EDG  (PREP_B2R + E_TOT)
__global__ void k_prep(const float* __restrict__ W_heads, const float* __restrict__ W_entities,
                       const float* __restrict__ gat_W, const float* __restrict__ out_W,
                       const int* __restrict__ edge_index, const int* __restrict__ ind2) {
    int i = blockIdx.x * blockDim.x + threadIdx.x;
    if (i < PREP_B1) {
        int idx = i;
        int k = idx / 768, c = idx % 768;
        float v;
        if (c < 512) {
            int part = c >> 8;
            int cc = c & 255;
            int h = cc >> 6, d = cc & 63;
            v = W_heads[h*384*64 + (part*128 + k)*64 + d];
        } else {
            v = W_entities[k*256 + (c - 512)];
        }
        g_B1[idx] = v;
    } else if (i < PREP_B1R) {
        int idx = i - PREP_B1;
        int k = idx / 512, c = idx % 512;
        float v;
        if (c < 256) {
            int h = c >> 6, d = c & 63;
            v = W_heads[h*384*64 + (256 + k)*64 + d];
        } else {
            v = gat_W[k*256 + (c - 256)];
        }
        g_B1r[idx] = v;
    } else if (i < PREP_B2) {
        int idx = i - PREP_B1R;
        int k = idx / 512, c = idx % 512;
        g_B2[idx] = (c < 256) ? out_W[k*256 + c] : out_W[(256 + k)*256 + (c - 256)];
    } else if (i < PREP_B2R) {
        int idx = i - PREP_B2;
        g_B2r[idx] = out_W[512*256 + idx];
    } else if (i < PREP_EDG) {
        int e = i - PREP_B2R;
        int r, c;
        if (e < E_DIR) { r = edge_index[E_DIR + e]; c = edge_index[e]; }
        else { int j = e - E_DIR; r = ind2[j*4 + 3]; c = ind2[j*4 + 0]; }
        g_row[e] = r; g_col[e] = c;
        atomicAdd(&g_cnt[r], 1);
    }
}

#define SCAN_T 1024
__global__ void k_scan() {
    __shared__ int s[SCAN_T];
    int t = threadIdx.x;
    const int CH = (N_ENT + SCAN_T - 1) / SCAN_T;
    int beg = t * CH;
    int fin = beg + CH; if (fin > N_ENT) fin = N_ENT;
    int sum = 0;
    for (int i = beg; i < fin; i++) sum += g_cnt[i];
    s[t] = sum;
    __syncthreads();
    for (int o = 1; o < SCAN_T; o <<= 1) {
        int v = (t >= o) ? s[t - o] : 0;
        __syncthreads();
        s[t] += v;
        __syncthreads();
    }
    int run = s[t] - sum;
    for (int i = beg; i < fin; i++) {
        g_off[i] = run;
        g_pos[i] = run;
        run += g_cnt[i];
    }
    if (t == SCAN_T - 1) g_off[N_ENT] = E_TOT;
}

__global__ void k_scatter() {
    int e = blockIdx.x * blockDim.x + threadIdx.x;
    if (e >= E_TOT) return;
    int r = g_row[e];
    int slot = atomicAdd(&g_pos[r], 1);
    g_elist[slot] = e;
}

// ---------------- 3x-bf16 tensor-core GEMM, 2 CTAs/SM + fused attention-scalar epilogue ----------------
__global__ __launch_bounds__(256, 2) void gemm_bf16(
    const float* __restrict__ A, const float* __restrict__ B,
    float* C0, float* C1, float* C2, float* C3, float* C4, float* C5,
    const float* __restrict__ avec,
    float* S0, float* S1, float* S2, float* S3, float* S4, float* S5,
    int sb0, int sb1, int sb2, int sb3, int sb4, int sb5,
    int sstride, int sgroups,
    int M, int K, int lda, int N)
{
    __shared__ uint32_t Ah[128*20];
    __shared__ uint32_t Al[128*20];
    __shared__ uint32_t Bh[16*136];
    __shared__ uint32_t Bl[16*136];

    int tid  = threadIdx.x;
    int m0   = blockIdx.y * 128;
    int n0   = blockIdx.x * 128;
    int warp = tid >> 5;
    int lane = tid & 31;
    int g = lane >> 2;
    int t = lane & 3;
    int wm = warp >> 1;
    int wn = warp & 1;

    float* Cb;
    float* Sb;
    int sbase;
    switch (blockIdx.x) {
        case 0: Cb = C0; Sb = S0; sbase = sb0; break;
        case 1: Cb = C1; Sb = S1; sbase = sb1; break;
        case 2: Cb = C2; Sb = S2; sbase = sb2; break;
        case 3: Cb = C3; Sb = S3; sbase = sb3; break;
        case 4: Cb = C4; Sb = S4; sbase = sb4; break;
        default: Cb = C5; Sb = S5; sbase = sb5; break;
    }

    float acc[2][8][4];
    #pragma unroll
    for (int i = 0; i < 2; i++)
        #pragma unroll
        for (int j = 0; j < 8; j++)
            #pragma unroll
            for (int q = 0; q < 4; q++) acc[i][j][q] = 0.f;

    for (int k0 = 0; k0 < K; k0 += 32) {
        #pragma unroll
        for (int i = 0; i < 4; i++) {
            int s = tid + i*256;
            int row = s >> 3;
            int w2  = (s & 7) << 1;
            float4 v = make_float4(0.f, 0.f, 0.f, 0.f);
            if (m0 + row < M)
                v = *(const float4*)(A + (size_t)(m0 + row)*lda + k0 + (w2 << 1));
            uint32_t h0, l0, h1, l1;
            split2(v.x, v.y, h0, l0);
            split2(v.z, v.w, h1, l1);
            Ah[row*20 + w2]     = h0;
            Ah[row*20 + w2 + 1] = h1;
            Al[row*20 + w2]     = l0;
            Al[row*20 + w2 + 1] = l1;
        }
        #pragma unroll
        for (int i = 0; i < 2; i++) {
            int s = tid + i*256;
            int wr = s >> 5;
            int n4 = (s & 31) << 2;
            const float* b0p = B + (size_t)(k0 + 2*wr)*N + n0 + n4;
            float4 r0 = *(const float4*)(b0p);
            float4 r1 = *(const float4*)(b0p + N);
            uint32_t h, l;
            split2(r0.x, r1.x, h, l); Bh[wr*136 + n4]     = h; Bl[wr*136 + n4]     = l;
            split2(r0.y, r1.y, h, l); Bh[wr*136 + n4 + 1] = h; Bl[wr*136 + n4 + 1] = l;
            split2(r0.z, r1.z, h, l); Bh[wr*136 + n4 + 2] = h; Bl[wr*136 + n4 + 2] = l;
            split2(r0.w, r1.w, h, l); Bh[wr*136 + n4 + 3] = h; Bl[wr*136 + n4 + 3] = l;
        }
        __syncthreads();

        #pragma unroll
        for (int ks = 0; ks < 2; ks++) {
            int kw = ks * 8;
            uint32_t ahi[2][4], alo[2][4];
            #pragma unroll
            for (int i = 0; i < 2; i++) {
                int rb = wm*32 + i*16;
                ahi[i][0] = Ah[(rb + g)*20     + kw + t];
                ahi[i][1] = Ah[(rb + g + 8)*20 + kw + t];
                ahi[i][2] = Ah[(rb + g)*20     + kw + t + 4];
                ahi[i][3] = Ah[(rb + g + 8)*20 + kw + t + 4];
                alo[i][0] = Al[(rb + g)*20     + kw + t];
                alo[i][1] = Al[(rb + g + 8)*20 + kw + t];
                alo[i][2] = Al[(rb + g)*20     + kw + t + 4];
                alo[i][3] = Al[(rb + g + 8)*20 + kw + t + 4];
            }
            // B fragments loaded per-j to keep live registers low (2 CTAs/SM)
            #pragma unroll
            for (int j = 0; j < 8; j++) {
                int nb = wn*64 + j*8 + g;
                uint32_t bh[2], bl[2];
                bh[0] = Bh[(kw + t)*136     + nb];
                bh[1] = Bh[(kw + t + 4)*136 + nb];
                bl[0] = Bl[(kw + t)*136     + nb];
                bl[1] = Bl[(kw + t + 4)*136 + nb];
                #pragma unroll
                for (int i = 0; i < 2; i++) {
                    mma16(acc[i][j], ahi[i], bh);
                    mma16(acc[i][j], ahi[i], bl);
                    mma16(acc[i][j], alo[i], bh);
                }
            }
        }
        __syncthreads();
    }

    // store C
    #pragma unroll
    for (int i = 0; i < 2; i++) {
        int r0 = m0 + wm*32 + i*16 + g;
        #pragma unroll
        for (int j = 0; j < 8; j++) {
            int col = wn*64 + j*8 + 2*t;
            if (r0 < M)
                *(float2*)(Cb + (size_t)r0*D_EMB + col) = make_float2(acc[i][j][0], acc[i][j][1]);
            if (r0 + 8 < M)
                *(float2*)(Cb + (size_t)(r0 + 8)*D_EMB + col) = make_float2(acc[i][j][2], acc[i][j][3]);
        }
    }

    // fused attention-scalar epilogue
    if (Sb) {
        float av0[8], av1[8];
        #pragma unroll
        for (int j = 0; j < 8; j++) {
            int col = n0 + wn*64 + j*8 + 2*t;
            av0[j] = avec[col & 255];
            av1[j] = avec[(col + 1) & 255];
        }
        int gidx = sbase + ((sgroups == 2) ? wn : 0);
        #pragma unroll
        for (int i = 0; i < 2; i++) {
            int r0 = m0 + wm*32 + i*16 + g;
            float d0 = 0.f, d1 = 0.f;
            #pragma unroll
            for (int j = 0; j < 8; j++) {
                d0 += acc[i][j][0]*av0[j] + acc[i][j][1]*av1[j];
                d1 += acc[i][j][2]*av0[j] + acc[i][j][3]*av1[j];
            }
            if (r0 < M)     atomicAdd(Sb + (size_t)r0*sstride + gidx, d0);
            if (r0 + 8 < M) atomicAdd(Sb + (size_t)(r0 + 8)*sstride + gidx, d1);
        }
    }
}

// ---------------- layer-1 single-pass row kernel, 2 warps per node ----------------
__global__ void k_row1(const int* __restrict__ et, const int* __restrict__ ind2) {
    int w_g  = (blockIdx.x * blockDim.x + threadIdx.x) >> 5;
    int lane = threadIdx.x & 31;
    if (w_g >= 2*N_ENT) return;
    int v    = w_g >> 1;
    int f    = ((w_g & 1) << 5) + lane;
    int h    = f >> 4;
    int off = g_off[v];
    int d   = g_off[v+1] - off;

    float srH = g_sr[v*NH + h];

    float4 acc = make_float4(0.f,0.f,0.f,0.f);
    float ws = 0.f;

    for (int i = 0; i < d; i++) {
        int e = g_elist[off + i];
        int c = g_col[e];
        float scH = g_sc[c*NH + h];
        float seH;
        const float4* hc = (const float4*)(g_hc + (size_t)c*D_EMB);
        float4 w0 = hc[f];
        float4 p0;
        if (e < E_DIR) {
            int tt = et[e];
            seH = g_srel[tt*NH + h];
            p0 = ((const float4*)(g_relp + tt*D_EMB))[f];
        } else {
            int j = e - E_DIR;
            int t0 = ind2[j*4+1], t1 = ind2[j*4+2];
            seH = g_srel[t0*NH + h] + g_srel[t1*NH + h];
            float4 q0 = ((const float4*)(g_relp + t0*D_EMB))[f];
            float4 q1 = ((const float4*)(g_relp + t1*D_EMB))[f];
            p0 = make_float4(q0.x+q1.x, q0.y+q1.y, q0.z+q1.z, q0.w+q1.w);
        }
        float z = srH + scH + seH;
        z = (z>0.f)?z:0.2f*z;
        float w = __expf(z);
        ws += w;
        acc.x += w*(w0.x+p0.x); acc.y += w*(w0.y+p0.y);
        acc.z += w*(w0.z+p0.z); acc.w += w*(w0.w+p0.w);
    }

    float inv = 1.f/(ws + 1e-16f);
    acc.x *= inv; acc.y *= inv; acc.z *= inv; acc.w *= inv;

    if (d > 0) {
        float4 hrv = ((const float4*)(g_hr + (size_t)v*D_EMB))[f];
        acc.x += hrv.x; acc.y += hrv.y; acc.z += hrv.z; acc.w += hrv.w;
    }
    acc.x = (acc.x>0.f)?acc.x:expm1f(acc.x);
    acc.y = (acc.y>0.f)?acc.y:expm1f(acc.y);
    acc.z = (acc.z>0.f)?acc.z:expm1f(acc.z);
    acc.w = (acc.w>0.f)?acc.w:expm1f(acc.w);
    ((float4*)(g_x + (size_t)v*D_EMB))[f] = acc;
}

// ---------------- layer-2 single-pass row kernel, 2 warps per node ----------------
__global__ void k_row2(const int* __restrict__ et, const int* __restrict__ ind2) {
    int w_g  = (blockIdx.x * blockDim.x + threadIdx.x) >> 5;
    int lane = threadIdx.x & 31;
    if (w_g >= 2*N_ENT) return;
    int v = w_g >> 1;
    int f = ((w_g & 1) << 5) + lane;
    int off = g_off[v];
    int d   = g_off[v+1] - off;

    float srv = g_s2r[v];

    float4 acc = make_float4(0.f,0.f,0.f,0.f);
    float ws = 0.f;

    for (int i = 0; i < d; i++) {
        int e = g_elist[off + i];
        int c = g_col[e];
        float se;
        float4 w0 = ((const float4*)(g_pcol + (size_t)c*D_EMB))[f];
        float4 p0;
        if (e < E_DIR) {
            int tt = et[e];
            se = g_srel2[tt];
            p0 = ((const float4*)(g_rel2p + tt*D_EMB))[f];
        } else {
            int j = e - E_DIR;
            int t0 = ind2[j*4+1], t1 = ind2[j*4+2];
            se = g_srel2[t0] + g_srel2[t1];
            float4 q0 = ((const float4*)(g_rel2p + t0*D_EMB))[f];
            float4 q1 = ((const float4*)(g_rel2p + t1*D_EMB))[f];
            p0 = make_float4(q0.x+q1.x, q0.y+q1.y, q0.z+q1.z, q0.w+q1.w);
        }
        float z = srv + g_s2c[c] + se;
        z = (z>0.f)?z:0.2f*z;
        float a = __expf(z);
        ws += a;
        acc.x += a*(w0.x+p0.x); acc.y += a*(w0.y+p0.y);
        acc.z += a*(w0.z+p0.z); acc.w += a*(w0.w+p0.w);
    }

    float inv = 1.f/(ws + 1e-16f);
    acc.x *= inv; acc.y *= inv; acc.z *= inv; acc.w *= inv;

    if (d > 0) {
        float4 hv = ((const float4*)(g_prow + (size_t)v*D_EMB))[f];
        acc.x += hv.x; acc.y += hv.y; acc.z += hv.z; acc.w += hv.w;
    }
    float4 ev = ((const float4*)(g_ent + (size_t)v*D_EMB))[f];
    acc.x = ((acc.x>0.f)?acc.x:expm1f(acc.x)) + ev.x;
    acc.y = ((acc.y>0.f)?acc.y:expm1f(acc.y)) + ev.y;
    acc.z = ((acc.z>0.f)?acc.z:expm1f(acc.z)) + ev.z;
    acc.w = ((acc.w>0.f)?acc.w:expm1f(acc.w)) + ev.w;
    ((float4*)(g_x + (size_t)v*D_EMB))[f] = acc;
}

// ---------------- BN stats + output ----------------
__global__ void k_stats() {
    int j = threadIdx.x;
    int v0 = blockIdx.x * 200;
    float s = 0.f, sq = 0.f;
    for (int v = v0; v < v0 + 200 && v < N_ENT; v++) {
        float z = g_x[(size_t)v*D_EMB + j];
        s += z; sq += z*z;
    }
    atomicAdd(&g_colsum[j], s);
    atomicAdd(&g_colsq[j], sq);
}

__global__ void k_bn_out(const float* __restrict__ gamma, const float* __restrict__ beta,
                         float* __restrict__ out) {
    int i = blockIdx.x * blockDim.x + threadIdx.x;
    if (i < N_ENT*D_EMB) {
        int j = i & 255;
        float mu  = g_colsum[j] * (1.f/N_ENT);
        float var = g_colsq[j] * (1.f/N_ENT) - mu*mu;
        out[i] = (g_x[i] - mu) * rsqrtf(var + 1e-5f) * gamma[j] + beta[j];
    } else if (i < N_ENT*D_EMB + N_REL*D_EMB) {
        out[i] = g_r[i - N_ENT*D_EMB];
    }
}

// ---------------- launch ----------------
extern "C" void kernel_launch(void* const* d_in, const int* in_sizes, int n_in,
                              void* d_out, int out_size) {
    const int*   edge_index = (const int*)d_in[0];
    const int*   edge_type  = (const int*)d_in[1];
    const int*   ind2       = (const int*)d_in[2];
    const float* init_embed = (const float*)d_in[3];
    const float* init_rel   = (const float*)d_in[4];
    const float* W_heads    = (const float*)d_in[5];
    const float* a_heads    = (const float*)d_in[6];
    const float* gat_W      = (const float*)d_in[7];
    const float* out_W      = (const float*)d_in[8];
    const float* out_a      = (const float*)d_in[9];
    const float* W_entities = (const float*)d_in[10];
    const float* bn_gamma   = (const float*)d_in[11];
    const float* bn_beta    = (const float*)d_in[12];
    float* out = (float*)d_out;

    float *p_hr, *p_hc, *p_ent, *p_prow, *p_pcol, *p_relp, *p_r, *p_rel2p, *p_x;
    float *p_B1, *p_B1r, *p_B2, *p_B2r;
    float *p_sr, *p_sc, *p_srel, *p_s2r, *p_s2c, *p_srel2;
    cudaGetSymbolAddress((void**)&p_hr,    g_hr);
    cudaGetSymbolAddress((void**)&p_hc,    g_hc);
    cudaGetSymbolAddress((void**)&p_ent,   g_ent);
    cudaGetSymbolAddress((void**)&p_prow,  g_prow);
    cudaGetSymbolAddress((void**)&p_pcol,  g_pcol);
    cudaGetSymbolAddress((void**)&p_relp,  g_relp);
    cudaGetSymbolAddress((void**)&p_r,     g_r);
    cudaGetSymbolAddress((void**)&p_rel2p, g_rel2p);
    cudaGetSymbolAddress((void**)&p_x,     g_x);
    cudaGetSymbolAddress((void**)&p_B1,    g_B1);
    cudaGetSymbolAddress((void**)&p_B1r,   g_B1r);
    cudaGetSymbolAddress((void**)&p_B2,    g_B2);
    cudaGetSymbolAddress((void**)&p_B2r,   g_B2r);
    cudaGetSymbolAddress((void**)&p_sr,    g_sr);
    cudaGetSymbolAddress((void**)&p_sc,    g_sc);
    cudaGetSymbolAddress((void**)&p_srel,  g_srel);
    cudaGetSymbolAddress((void**)&p_s2r,   g_s2r);
    cudaGetSymbolAddress((void**)&p_s2c,   g_s2c);
    cudaGetSymbolAddress((void**)&p_srel2, g_srel2);

    const int TB = 256;
    k_init<<<160, TB>>>();
    k_prep<<<(PREP_EDG + TB-1)/TB, TB>>>(W_heads, W_entities, gat_W, out_W, edge_index, ind2);
    k_scan<<<1, SCAN_T>>>();
    k_scatter<<<(E_TOT + TB-1)/TB, TB>>>();

    // layer-1 GEMMs (scalars fused)
    gemm_bf16<<<dim3(6, (N_ENT + 127)/128), 256>>>(
        init_embed, p_B1,
        p_hr, p_hr + 128, p_hc, p_hc + 128, p_ent, p_ent + 128,
        a_heads,
        p_sr, p_sr, p_sc, p_sc, (float*)0, (float*)0,
        0, 2, 0, 2, 0, 0,
        NH, 2,
        N_ENT, 128, 128, 768);
    gemm_bf16<<<dim3(4, (N_REL + 127)/128), 256>>>(
        init_rel, p_B1r,
        p_relp, p_relp + 128, p_r, p_r + 128, p_r, p_r,
        a_heads,
        p_srel, p_srel, (float*)0, (float*)0, (float*)0, (float*)0,
        0, 2, 0, 0, 0, 0,
        NH, 2,
        N_REL, 128, 128, 512);

    // layer-1 attention
    k_row1<<<(2*N_ENT*32 + TB-1)/TB, TB>>>(edge_type, ind2);

    // layer-2 GEMMs (scalars fused)
    gemm_bf16<<<dim3(4, (N_ENT + 127)/128), 256>>>(
        p_x, p_B2,
        p_prow, p_prow + 128, p_pcol, p_pcol + 128, p_pcol, p_pcol,
        out_a,
        p_s2r, p_s2r, p_s2c, p_s2c, (float*)0, (float*)0,
        0, 0, 0, 0, 0, 0,
        1, 1,
        N_ENT, 256, 256, 512);
    gemm_bf16<<<dim3(2, (N_REL + 127)/128), 256>>>(
        p_r, p_B2r,
        p_rel2p, p_rel2p + 128, p_rel2p, p_rel2p, p_rel2p, p_rel2p,
        out_a,
        p_srel2, p_srel2, (float*)0, (float*)0, (float*)0, (float*)0,
        0, 0, 0, 0, 0, 0,
        1, 1,
        N_REL, 256, 256, 256);

    // layer-2 attention
    k_row2<<<(2*N_ENT*32 + TB-1)/TB, TB>>>(edge_type, ind2);

    k_stats<<<200, 256>>>();
    k_bn_out<<<(N_ENT*D_EMB + N_REL*D_EMB + TB-1)/TB, TB>>>(bn_gamma, bn_beta, out);
}

// round 17
// speedup vs baseline: 1.2041x; 1.0530x over previous
#include <cuda_runtime.h>
#include <math.h>
#include <stdint.h>

#define N_ENT  40000
#define N_REL  500
#define E_DIR  200000
#define E_TOT  250000
#define D_IN   128
#define D_EMB  256
#define NH     4

// ---------------- device scratch ----------------
__device__ float g_hr[N_ENT*D_EMB];
__device__ float g_hc[N_ENT*D_EMB];
__device__ float g_ent[N_ENT*D_EMB];
__device__ float g_prow[N_ENT*D_EMB];
__device__ float g_pcol[N_ENT*D_EMB];
__device__ float g_relp[N_REL*D_EMB];
__device__ float g_r[N_REL*D_EMB];
__device__ float g_rel2p[N_REL*D_EMB];
__device__ float g_x[N_ENT*D_EMB];
__device__ float g_B1[128*768];
__device__ float g_B1r[128*512];
__device__ float g_B2[256*512];
__device__ float g_B2r[256*256];
__device__ float g_sr[N_ENT*NH];
__device__ float g_sc[N_ENT*NH];
__device__ float g_srel[N_REL*NH];
__device__ float g_s2r[N_ENT];
__device__ float g_s2c[N_ENT];
__device__ float g_srel2[N_REL];
__device__ int   g_row[E_TOT];
__device__ int   g_col[E_TOT];
__device__ int   g_cnt[N_ENT];
__device__ int   g_off[N_ENT+1];
__device__ int   g_pos[N_ENT];
__device__ int   g_elist[E_TOT];
__device__ float g_colsum[D_EMB];
__device__ float g_colsq[D_EMB];

// ---------------- helpers ----------------
__device__ __forceinline__ void split2(float x, float y, uint32_t& hi, uint32_t& lo) {
    uint32_t xb = __float_as_uint(x) & 0xffff0000u;
    uint32_t yb = __float_as_uint(y) & 0xffff0000u;
    hi = (xb >> 16) | yb;
    float lx = x - __uint_as_float(xb);
    float ly = y - __uint_as_float(yb);
    asm("cvt.rn.bf16x2.f32 %0, %1, %2;" : "=r"(lo) : "f"(ly), "f"(lx));
}

__device__ __forceinline__ void mma16(float* c, const uint32_t* a, const uint32_t* b) {
    asm volatile(
        "mma.sync.aligned.m16n8k16.row.col.f32.bf16.bf16.f32 "
        "{%0,%1,%2,%3},{%4,%5,%6,%7},{%8,%9},{%0,%1,%2,%3};"
        : "+f"(c[0]), "+f"(c[1]), "+f"(c[2]), "+f"(c[3])
        : "r"(a[0]), "r"(a[1]), "r"(a[2]), "r"(a[3]), "r"(b[0]), "r"(b[1]));
}

// ---------------- init: counters + scalar accumulators ----------------
__global__ void k_init() {
    int i = blockIdx.x * blockDim.x + threadIdx.x;
    int stride = gridDim.x * blockDim.x;
    for (int idx = i; idx < N_ENT*NH; idx += stride) { g_sr[idx] = 0.f; g_sc[idx] = 0.f; }
    for (int idx = i; idx < N_ENT; idx += stride) {
        g_cnt[idx] = 0; g_s2r[idx] = 0.f; g_s2c[idx] = 0.f;
    }
    for (int idx = i; idx < N_REL*NH; idx += stride) g_srel[idx] = 0.f;
    for (int idx = i; idx < N_REL; idx += stride) g_srel2[idx] = 0.f;
    if (i < D_EMB) { g_colsum[i] = 0.f; g_colsq[i] = 0.f; }
}

// ---------------- fused prep: all weight repacks + edge list build ----------------
#define PREP_B1   (128*768)
#define PREP_B1R  (PREP_B1 + 128*512)
#define PREP_B2   (PREP_B1R + 256*512)
#define PREP_B2R  (PREP_B2 + 256*256)
#define PREP_EDG  (PREP_B2R + E_TOT)
__global__ void k_prep(const float* __restrict__ W_heads, const float* __restrict__ W_entities,
                       const float* __restrict__ gat_W, const float* __restrict__ out_W,
                       const int* __restrict__ edge_index, const int* __restrict__ ind2) {
    int i = blockIdx.x * blockDim.x + threadIdx.x;
    if (i < PREP_B1) {
        int idx = i;
        int k = idx / 768, c = idx % 768;
        float v;
        if (c < 512) {
            int part = c >> 8;
            int cc = c & 255;
            int h = cc >> 6, d = cc & 63;
            v = W_heads[h*384*64 + (part*128 + k)*64 + d];
        } else {
            v = W_entities[k*256 + (c - 512)];
        }
        g_B1[idx] = v;
    } else if (i < PREP_B1R) {
        int idx = i - PREP_B1;
        int k = idx / 512, c = idx % 512;
        float v;
        if (c < 256) {
            int h = c >> 6, d = c & 63;
            v = W_heads[h*384*64 + (256 + k)*64 + d];
        } else {
            v = gat_W[k*256 + (c - 256)];
        }
        g_B1r[idx] = v;
    } else if (i < PREP_B2) {
        int idx = i - PREP_B1R;
        int k = idx / 512, c = idx % 512;
        g_B2[idx] = (c < 256) ? out_W[k*256 + c] : out_W[(256 + k)*256 + (c - 256)];
    } else if (i < PREP_B2R) {
        int idx = i - PREP_B2;
        g_B2r[idx] = out_W[512*256 + idx];
    } else if (i < PREP_EDG) {
        int e = i - PREP_B2R;
        int r, c;
        if (e < E_DIR) { r = edge_index[E_DIR + e]; c = edge_index[e]; }
        else { int j = e - E_DIR; r = ind2[j*4 + 3]; c = ind2[j*4 + 0]; }
        g_row[e] = r; g_col[e] = c;
        atomicAdd(&g_cnt[r], 1);
    }
}

#define SCAN_T 1024
__global__ void k_scan() {
    __shared__ int s[SCAN_T];
    int t = threadIdx.x;
    const int CH = (N_ENT + SCAN_T - 1) / SCAN_T;
    int beg = t * CH;
    int fin = beg + CH; if (fin > N_ENT) fin = N_ENT;
    int sum = 0;
    for (int i = beg; i < fin; i++) sum += g_cnt[i];
    s[t] = sum;
    __syncthreads();
    for (int o = 1; o < SCAN_T; o <<= 1) {
        int v = (t >= o) ? s[t - o] : 0;
        __syncthreads();
        s[t] += v;
        __syncthreads();
    }
    int run = s[t] - sum;
    for (int i = beg; i < fin; i++) {
        g_off[i] = run;
        g_pos[i] = run;
        run += g_cnt[i];
    }
    if (t == SCAN_T - 1) g_off[N_ENT] = E_TOT;
}

__global__ void k_scatter() {
    int e = blockIdx.x * blockDim.x + threadIdx.x;
    if (e >= E_TOT) return;
    int r = g_row[e];
    int slot = atomicAdd(&g_pos[r], 1);
    g_elist[slot] = e;
}

// ---------------- GEMM job descriptor (passed by value) ----------------
struct GemmJob {
    const float* A;
    const float* B;
    float* C[6];
    const float* avec;
    float* S[6];
    int sb[6];
    int sstride, sgroups;
    int M, K, lda, N;
    int ytiles;
};

// ---------------- 3x-bf16 tensor-core GEMM, 2 CTAs/SM, dual-job, fused scalar epilogue ----------------
__global__ __launch_bounds__(256, 2) void gemm_bf16(GemmJob j0, GemmJob j1)
{
    __shared__ uint32_t Ah[128*20];
    __shared__ uint32_t Al[128*20];
    __shared__ uint32_t Bh[16*136];
    __shared__ uint32_t Bl[16*136];

    int by = blockIdx.y;
    const GemmJob& jb = (by < j0.ytiles) ? j0 : j1;
    int yt = (by < j0.ytiles) ? by : (by - j0.ytiles);
    int n0 = blockIdx.x * 128;
    if (n0 >= jb.N) return;

    int tid  = threadIdx.x;
    int m0   = yt * 128;
    int warp = tid >> 5;
    int lane = tid & 31;
    int g = lane >> 2;
    int t = lane & 3;
    int wm = warp >> 1;
    int wn = warp & 1;

    const float* A = jb.A;
    const float* B = jb.B;
    int M = jb.M, K = jb.K, lda = jb.lda, N = jb.N;
    float* Cb = jb.C[blockIdx.x];
    float* Sb = jb.S[blockIdx.x];
    int sbase = jb.sb[blockIdx.x];

    float acc[2][8][4];
    #pragma unroll
    for (int i = 0; i < 2; i++)
        #pragma unroll
        for (int j = 0; j < 8; j++)
            #pragma unroll
            for (int q = 0; q < 4; q++) acc[i][j][q] = 0.f;

    for (int k0 = 0; k0 < K; k0 += 32) {
        #pragma unroll
        for (int i = 0; i < 4; i++) {
            int s = tid + i*256;
            int row = s >> 3;
            int w2  = (s & 7) << 1;
            float4 v = make_float4(0.f, 0.f, 0.f, 0.f);
            if (m0 + row < M)
                v = *(const float4*)(A + (size_t)(m0 + row)*lda + k0 + (w2 << 1));
            uint32_t h0, l0, h1, l1;
            split2(v.x, v.y, h0, l0);
            split2(v.z, v.w, h1, l1);
            Ah[row*20 + w2]     = h0;
            Ah[row*20 + w2 + 1] = h1;
            Al[row*20 + w2]     = l0;
            Al[row*20 + w2 + 1] = l1;
        }
        #pragma unroll
        for (int i = 0; i < 2; i++) {
            int s = tid + i*256;
            int wr = s >> 5;
            int n4 = (s & 31) << 2;
            const float* b0p = B + (size_t)(k0 + 2*wr)*N + n0 + n4;
            float4 r0 = *(const float4*)(b0p);
            float4 r1 = *(const float4*)(b0p + N);
            uint32_t h, l;
            split2(r0.x, r1.x, h, l); Bh[wr*136 + n4]     = h; Bl[wr*136 + n4]     = l;
            split2(r0.y, r1.y, h, l); Bh[wr*136 + n4 + 1] = h; Bl[wr*136 + n4 + 1] = l;
            split2(r0.z, r1.z, h, l); Bh[wr*136 + n4 + 2] = h; Bl[wr*136 + n4 + 2] = l;
            split2(r0.w, r1.w, h, l); Bh[wr*136 + n4 + 3] = h; Bl[wr*136 + n4 + 3] = l;
        }
        __syncthreads();

        #pragma unroll
        for (int ks = 0; ks < 2; ks++) {
            int kw = ks * 8;
            uint32_t ahi[2][4], alo[2][4];
            #pragma unroll
            for (int i = 0; i < 2; i++) {
                int rb = wm*32 + i*16;
                ahi[i][0] = Ah[(rb + g)*20     + kw + t];
                ahi[i][1] = Ah[(rb + g + 8)*20 + kw + t];
                ahi[i][2] = Ah[(rb + g)*20     + kw + t + 4];
                ahi[i][3] = Ah[(rb + g + 8)*20 + kw + t + 4];
                alo[i][0] = Al[(rb + g)*20     + kw + t];
                alo[i][1] = Al[(rb + g + 8)*20 + kw + t];
                alo[i][2] = Al[(rb + g)*20     + kw + t + 4];
                alo[i][3] = Al[(rb + g + 8)*20 + kw + t + 4];
            }
            #pragma unroll
            for (int j = 0; j < 8; j++) {
                int nb = wn*64 + j*8 + g;
                uint32_t bh[2], bl[2];
                bh[0] = Bh[(kw + t)*136     + nb];
                bh[1] = Bh[(kw + t + 4)*136 + nb];
                bl[0] = Bl[(kw + t)*136     + nb];
                bl[1] = Bl[(kw + t + 4)*136 + nb];
                #pragma unroll
                for (int i = 0; i < 2; i++) {
                    mma16(acc[i][j], ahi[i], bh);
                    mma16(acc[i][j], ahi[i], bl);
                    mma16(acc[i][j], alo[i], bh);
                }
            }
        }
        __syncthreads();
    }

    // store C
    #pragma unroll
    for (int i = 0; i < 2; i++) {
        int r0 = m0 + wm*32 + i*16 + g;
        #pragma unroll
        for (int j = 0; j < 8; j++) {
            int col = wn*64 + j*8 + 2*t;
            if (r0 < M)
                *(float2*)(Cb + (size_t)r0*D_EMB + col) = make_float2(acc[i][j][0], acc[i][j][1]);
            if (r0 + 8 < M)
                *(float2*)(Cb + (size_t)(r0 + 8)*D_EMB + col) = make_float2(acc[i][j][2], acc[i][j][3]);
        }
    }

    // fused attention-scalar epilogue
    if (Sb) {
        const float* avec = jb.avec;
        float av0[8], av1[8];
        #pragma unroll
        for (int j = 0; j < 8; j++) {
            int col = n0 + wn*64 + j*8 + 2*t;
            av0[j] = avec[col & 255];
            av1[j] = avec[(col + 1) & 255];
        }
        int gidx = sbase + ((jb.sgroups == 2) ? wn : 0);
        #pragma unroll
        for (int i = 0; i < 2; i++) {
            int r0 = m0 + wm*32 + i*16 + g;
            float d0 = 0.f, d1 = 0.f;
            #pragma unroll
            for (int j = 0; j < 8; j++) {
                d0 += acc[i][j][0]*av0[j] + acc[i][j][1]*av1[j];
                d1 += acc[i][j][2]*av0[j] + acc[i][j][3]*av1[j];
            }
            if (r0 < M)     atomicAdd(Sb + (size_t)r0*jb.sstride + gidx, d0);
            if (r0 + 8 < M) atomicAdd(Sb + (size_t)(r0 + 8)*jb.sstride + gidx, d1);
        }
    }
}

// ---------------- layer-1 single-pass row kernel, 2 warps per node ----------------
__global__ void k_row1(const int* __restrict__ et, const int* __restrict__ ind2) {
    int w_g  = (blockIdx.x * blockDim.x + threadIdx.x) >> 5;
    int lane = threadIdx.x & 31;
    if (w_g >= 2*N_ENT) return;
    int v    = w_g >> 1;
    int f    = ((w_g & 1) << 5) + lane;
    int h    = f >> 4;
    int off = g_off[v];
    int d   = g_off[v+1] - off;

    float srH = g_sr[v*NH + h];

    float4 acc = make_float4(0.f,0.f,0.f,0.f);
    float ws = 0.f;

    for (int i = 0; i < d; i++) {
        int e = g_elist[off + i];
        int c = g_col[e];
        float scH = g_sc[c*NH + h];
        float seH;
        const float4* hc = (const float4*)(g_hc + (size_t)c*D_EMB);
        float4 w0 = hc[f];
        float4 p0;
        if (e < E_DIR) {
            int tt = et[e];
            seH = g_srel[tt*NH + h];
            p0 = ((const float4*)(g_relp + tt*D_EMB))[f];
        } else {
            int j = e - E_DIR;
            int t0 = ind2[j*4+1], t1 = ind2[j*4+2];
            seH = g_srel[t0*NH + h] + g_srel[t1*NH + h];
            float4 q0 = ((const float4*)(g_relp + t0*D_EMB))[f];
            float4 q1 = ((const float4*)(g_relp + t1*D_EMB))[f];
            p0 = make_float4(q0.x+q1.x, q0.y+q1.y, q0.z+q1.z, q0.w+q1.w);
        }
        float z = srH + scH + seH;
        z = (z>0.f)?z:0.2f*z;
        float w = __expf(z);
        ws += w;
        acc.x += w*(w0.x+p0.x); acc.y += w*(w0.y+p0.y);
        acc.z += w*(w0.z+p0.z); acc.w += w*(w0.w+p0.w);
    }

    float inv = 1.f/(ws + 1e-16f);
    acc.x *= inv; acc.y *= inv; acc.z *= inv; acc.w *= inv;

    if (d > 0) {
        float4 hrv = ((const float4*)(g_hr + (size_t)v*D_EMB))[f];
        acc.x += hrv.x; acc.y += hrv.y; acc.z += hrv.z; acc.w += hrv.w;
    }
    acc.x = (acc.x>0.f)?acc.x:expm1f(acc.x);
    acc.y = (acc.y>0.f)?acc.y:expm1f(acc.y);
    acc.z = (acc.z>0.f)?acc.z:expm1f(acc.z);
    acc.w = (acc.w>0.f)?acc.w:expm1f(acc.w);
    ((float4*)(g_x + (size_t)v*D_EMB))[f] = acc;
}

// ---------------- layer-2 single-pass row kernel, 2 warps per node ----------------
__global__ void k_row2(const int* __restrict__ et, const int* __restrict__ ind2) {
    int w_g  = (blockIdx.x * blockDim.x + threadIdx.x) >> 5;
    int lane = threadIdx.x & 31;
    if (w_g >= 2*N_ENT) return;
    int v = w_g >> 1;
    int f = ((w_g & 1) << 5) + lane;
    int off = g_off[v];
    int d   = g_off[v+1] - off;

    float srv = g_s2r[v];

    float4 acc = make_float4(0.f,0.f,0.f,0.f);
    float ws = 0.f;

    for (int i = 0; i < d; i++) {
        int e = g_elist[off + i];
        int c = g_col[e];
        float se;
        float4 w0 = ((const float4*)(g_pcol + (size_t)c*D_EMB))[f];
        float4 p0;
        if (e < E_DIR) {
            int tt = et[e];
            se = g_srel2[tt];
            p0 = ((const float4*)(g_rel2p + tt*D_EMB))[f];
        } else {
            int j = e - E_DIR;
            int t0 = ind2[j*4+1], t1 = ind2[j*4+2];
            se = g_srel2[t0] + g_srel2[t1];
            float4 q0 = ((const float4*)(g_rel2p + t0*D_EMB))[f];
            float4 q1 = ((const float4*)(g_rel2p + t1*D_EMB))[f];
            p0 = make_float4(q0.x+q1.x, q0.y+q1.y, q0.z+q1.z, q0.w+q1.w);
        }
        float z = srv + g_s2c[c] + se;
        z = (z>0.f)?z:0.2f*z;
        float a = __expf(z);
        ws += a;
        acc.x += a*(w0.x+p0.x); acc.y += a*(w0.y+p0.y);
        acc.z += a*(w0.z+p0.z); acc.w += a*(w0.w+p0.w);
    }

    float inv = 1.f/(ws + 1e-16f);
    acc.x *= inv; acc.y *= inv; acc.z *= inv; acc.w *= inv;

    if (d > 0) {
        float4 hv = ((const float4*)(g_prow + (size_t)v*D_EMB))[f];
        acc.x += hv.x; acc.y += hv.y; acc.z += hv.z; acc.w += hv.w;
    }
    float4 ev = ((const float4*)(g_ent + (size_t)v*D_EMB))[f];
    acc.x = ((acc.x>0.f)?acc.x:expm1f(acc.x)) + ev.x;
    acc.y = ((acc.y>0.f)?acc.y:expm1f(acc.y)) + ev.y;
    acc.z = ((acc.z>0.f)?acc.z:expm1f(acc.z)) + ev.z;
    acc.w = ((acc.w>0.f)?acc.w:expm1f(acc.w)) + ev.w;
    ((float4*)(g_x + (size_t)v*D_EMB))[f] = acc;
}

// ---------------- BN stats + output ----------------
__global__ void k_stats() {
    int j = threadIdx.x;
    int v0 = blockIdx.x * 200;
    float s = 0.f, sq = 0.f;
    for (int v = v0; v < v0 + 200 && v < N_ENT; v++) {
        float z = g_x[(size_t)v*D_EMB + j];
        s += z; sq += z*z;
    }
    atomicAdd(&g_colsum[j], s);
    atomicAdd(&g_colsq[j], sq);
}

__global__ void k_bn_out(const float* __restrict__ gamma, const float* __restrict__ beta,
                         float* __restrict__ out) {
    int i = blockIdx.x * blockDim.x + threadIdx.x;
    if (i < N_ENT*D_EMB) {
        int j = i & 255;
        float mu  = g_colsum[j] * (1.f/N_ENT);
        float var = g_colsq[j] * (1.f/N_ENT) - mu*mu;
        out[i] = (g_x[i] - mu) * rsqrtf(var + 1e-5f) * gamma[j] + beta[j];
    } else if (i < N_ENT*D_EMB + N_REL*D_EMB) {
        out[i] = g_r[i - N_ENT*D_EMB];
    }
}

// ---------------- launch ----------------
extern "C" void kernel_launch(void* const* d_in, const int* in_sizes, int n_in,
                              void* d_out, int out_size) {
    const int*   edge_index = (const int*)d_in[0];
    const int*   edge_type  = (const int*)d_in[1];
    const int*   ind2       = (const int*)d_in[2];
    const float* init_embed = (const float*)d_in[3];
    const float* init_rel   = (const float*)d_in[4];
    const float* W_heads    = (const float*)d_in[5];
    const float* a_heads    = (const float*)d_in[6];
    const float* gat_W      = (const float*)d_in[7];
    const float* out_W      = (const float*)d_in[8];
    const float* out_a      = (const float*)d_in[9];
    const float* W_entities = (const float*)d_in[10];
    const float* bn_gamma   = (const float*)d_in[11];
    const float* bn_beta    = (const float*)d_in[12];
    float* out = (float*)d_out;

    float *p_hr, *p_hc, *p_ent, *p_prow, *p_pcol, *p_relp, *p_r, *p_rel2p, *p_x;
    float *p_B1, *p_B1r, *p_B2, *p_B2r;
    float *p_sr, *p_sc, *p_srel, *p_s2r, *p_s2c, *p_srel2;
    cudaGetSymbolAddress((void**)&p_hr,    g_hr);
    cudaGetSymbolAddress((void**)&p_hc,    g_hc);
    cudaGetSymbolAddress((void**)&p_ent,   g_ent);
    cudaGetSymbolAddress((void**)&p_prow,  g_prow);
    cudaGetSymbolAddress((void**)&p_pcol,  g_pcol);
    cudaGetSymbolAddress((void**)&p_relp,  g_relp);
    cudaGetSymbolAddress((void**)&p_r,     g_r);
    cudaGetSymbolAddress((void**)&p_rel2p, g_rel2p);
    cudaGetSymbolAddress((void**)&p_x,     g_x);
    cudaGetSymbolAddress((void**)&p_B1,    g_B1);
    cudaGetSymbolAddress((void**)&p_B1r,   g_B1r);
    cudaGetSymbolAddress((void**)&p_B2,    g_B2);
    cudaGetSymbolAddress((void**)&p_B2r,   g_B2r);
    cudaGetSymbolAddress((void**)&p_sr,    g_sr);
    cudaGetSymbolAddress((void**)&p_sc,    g_sc);
    cudaGetSymbolAddress((void**)&p_srel,  g_srel);
    cudaGetSymbolAddress((void**)&p_s2r,   g_s2r);
    cudaGetSymbolAddress((void**)&p_s2c,   g_s2c);
    cudaGetSymbolAddress((void**)&p_srel2, g_srel2);

    const int TB = 256;
    k_init<<<160, TB>>>();
    k_prep<<<(PREP_EDG + TB-1)/TB, TB>>>(W_heads, W_entities, gat_W, out_W, edge_index, ind2);
    k_scan<<<1, SCAN_T>>>();
    k_scatter<<<(E_TOT + TB-1)/TB, TB>>>();

    const int YT = (N_ENT + 127)/128;   // 313
    const int YR = (N_REL + 127)/128;   // 4

    // ----- layer-1 merged GEMM (main + rel) -----
    GemmJob m1{}, r1{};
    m1.A = init_embed; m1.B = p_B1;
    m1.C[0]=p_hr; m1.C[1]=p_hr+128; m1.C[2]=p_hc; m1.C[3]=p_hc+128; m1.C[4]=p_ent; m1.C[5]=p_ent+128;
    m1.avec = a_heads;
    m1.S[0]=p_sr; m1.S[1]=p_sr; m1.S[2]=p_sc; m1.S[3]=p_sc; m1.S[4]=0; m1.S[5]=0;
    m1.sb[0]=0; m1.sb[1]=2; m1.sb[2]=0; m1.sb[3]=2; m1.sb[4]=0; m1.sb[5]=0;
    m1.sstride = NH; m1.sgroups = 2;
    m1.M = N_ENT; m1.K = 128; m1.lda = 128; m1.N = 768; m1.ytiles = YT;

    r1.A = init_rel; r1.B = p_B1r;
    r1.C[0]=p_relp; r1.C[1]=p_relp+128; r1.C[2]=p_r; r1.C[3]=p_r+128; r1.C[4]=p_r; r1.C[5]=p_r;
    r1.avec = a_heads;
    r1.S[0]=p_srel; r1.S[1]=p_srel; r1.S[2]=0; r1.S[3]=0; r1.S[4]=0; r1.S[5]=0;
    r1.sb[0]=0; r1.sb[1]=2; r1.sb[2]=0; r1.sb[3]=0; r1.sb[4]=0; r1.sb[5]=0;
    r1.sstride = NH; r1.sgroups = 2;
    r1.M = N_REL; r1.K = 128; r1.lda = 128; r1.N = 512; r1.ytiles = YR;

    gemm_bf16<<<dim3(6, YT + YR), 256>>>(m1, r1);

    // layer-1 attention
    k_row1<<<(2*N_ENT*32 + TB-1)/TB, TB>>>(edge_type, ind2);

    // ----- layer-2 merged GEMM (main + rel) -----
    GemmJob m2{}, r2{};
    m2.A = p_x; m2.B = p_B2;
    m2.C[0]=p_prow; m2.C[1]=p_prow+128; m2.C[2]=p_pcol; m2.C[3]=p_pcol+128; m2.C[4]=p_pcol; m2.C[5]=p_pcol;
    m2.avec = out_a;
    m2.S[0]=p_s2r; m2.S[1]=p_s2r; m2.S[2]=p_s2c; m2.S[3]=p_s2c; m2.S[4]=0; m2.S[5]=0;
    m2.sb[0]=0; m2.sb[1]=0; m2.sb[2]=0; m2.sb[3]=0; m2.sb[4]=0; m2.sb[5]=0;
    m2.sstride = 1; m2.sgroups = 1;
    m2.M = N_ENT; m2.K = 256; m2.lda = 256; m2.N = 512; m2.ytiles = YT;

    r2.A = p_r; r2.B = p_B2r;
    r2.C[0]=p_rel2p; r2.C[1]=p_rel2p+128; r2.C[2]=p_rel2p; r2.C[3]=p_rel2p; r2.C[4]=p_rel2p; r2.C[5]=p_rel2p;
    r2.avec = out_a;
    r2.S[0]=p_srel2; r2.S[1]=p_srel2; r2.S[2]=0; r2.S[3]=0; r2.S[4]=0; r2.S[5]=0;
    r2.sb[0]=0; r2.sb[1]=0; r2.sb[2]=0; r2.sb[3]=0; r2.sb[4]=0; r2.sb[5]=0;
    r2.sstride = 1; r2.sgroups = 1;
    r2.M = N_REL; r2.K = 256; r2.lda = 256; r2.N = 256; r2.ytiles = YR;

    gemm_bf16<<<dim3(4, YT + YR), 256>>>(m2, r2);

    // layer-2 attention
    k_row2<<<(2*N_ENT*32 + TB-1)/TB, TB>>>(edge_type, ind2);

    k_stats<<<200, 256>>>();
    k_bn_out<<<(N_ENT*D_EMB + N_REL*D_EMB + TB-1)/TB, TB>>>(bn_gamma, bn_beta, out);
}